// round 5
// baseline (speedup 1.0000x reference)
#include <cuda_runtime.h>
#include <math.h>

// ---------------- problem constants ----------------
#define BB    8
#define MM    1024
#define DM    768
#define HH    12
#define DHD   64
#define RR    32
#define RFF   384
#define DFF   3072
#define BMTOT (BB*MM)          // 8192
#define NCAT  (3*HH*RR)        // 1152

// ---------------- scratch (device globals; no allocs allowed) ----------------
__device__ float g_Pt  [DM   * NCAT];     // permuted P: [DM, 1152]
__device__ float g_T   [BMTOT* NCAT];     // x @ Pt
__device__ float g_Q   [BMTOT* DM];       // [B,H,M,DH]
__device__ float g_K   [BMTOT* DM];
__device__ float g_V   [BMTOT* DM];
__device__ float g_attn[BMTOT* DM];       // [B,M,H*DH]
__device__ float g_mid [BMTOT* RFF];      // rank-384 intermediates (reused)
__device__ float g_tmp [BMTOT* DM];
__device__ float g_x1  [BMTOT* DM];
__device__ float g_hdn [BMTOT* DFF];

// ---------------- helpers ----------------
__device__ __forceinline__ float gelu_exact(float v) {
    return 0.5f * v * (1.0f + erff(v * 0.70710678118654752440f));
}

// ---------------- P permute: [H,DM,R] x3 -> [DM, 3*H*R] ----------------
__global__ void permuteP_kernel(const float* __restrict__ Pq,
                                const float* __restrict__ Pk,
                                const float* __restrict__ Pv,
                                float* __restrict__ Pt) {
    int idx = blockIdx.x * 256 + threadIdx.x;
    if (idx >= DM * NCAT) return;
    int d = idx / NCAT;
    int n = idx - d * NCAT;
    int which = n / (HH*RR);
    int hn = n - which * (HH*RR);
    int h = hn >> 5;           // /32
    int r = hn & 31;
    const float* P = (which == 0) ? Pq : (which == 1) ? Pk : Pv;
    Pt[idx] = P[(h * DM + d) * RR + r];
}

// ---------------- SGEMM 128x128x16, 8x8 split microtile, double-buffered ----------------
// C[M,N] = A[M,K] @ B[K,N] (+bias)(+gelu). Requires M%128==0, N%128==0, K%16==0.
template<bool GELU>
__global__ __launch_bounds__(256, 2)
void sgemm128_kernel(const float* __restrict__ A, const float* __restrict__ B,
                     const float* __restrict__ bias, float* __restrict__ C,
                     int Md, int Nd, int Kd) {
    __shared__ float As[2][16][132];   // [buf][k][row], 132 stride: f4-aligned, 2-way STS conflict only
    __shared__ float Bs[2][16][128];   // [buf][k][col]

    const int tid = threadIdx.x;
    const int rowBase = blockIdx.y * 128;
    const int colBase = blockIdx.x * 128;

    // load mappings
    const int a_r = tid >> 2;              // 0..63  (second f4: +64)
    const int a_c = (tid & 3) << 2;        // 0,4,8,12
    const int b_r = tid >> 5;              // 0..7   (second f4: +8)
    const int b_c = (tid & 31) << 2;       // 0..124

    const float* Ap0 = A + (size_t)(rowBase + a_r) * Kd + a_c;
    const float* Ap1 = Ap0 + (size_t)64 * Kd;
    const float* Bp0 = B + (size_t)b_r * Nd + colBase + b_c;
    const float* Bp1 = Bp0 + (size_t)8 * Nd;

    // compute mapping: split microtile. rows {ty*4+i, 64+ty*4+i}, cols {tx*4+j, 64+tx*4+j}
    const int ty = tid >> 4;    // 0..15
    const int tx = tid & 15;    // 0..15

    float acc[8][8];
    #pragma unroll
    for (int i = 0; i < 8; i++)
        #pragma unroll
        for (int j = 0; j < 8; j++) acc[i][j] = 0.0f;

    float4 pa0, pa1, pb0, pb1;
    pa0 = *(const float4*)Ap0;
    pa1 = *(const float4*)Ap1;
    pb0 = *(const float4*)Bp0;
    pb1 = *(const float4*)Bp1;

    // store buffer 0
    As[0][a_c + 0][a_r] = pa0.x; As[0][a_c + 1][a_r] = pa0.y;
    As[0][a_c + 2][a_r] = pa0.z; As[0][a_c + 3][a_r] = pa0.w;
    As[0][a_c + 0][a_r + 64] = pa1.x; As[0][a_c + 1][a_r + 64] = pa1.y;
    As[0][a_c + 2][a_r + 64] = pa1.z; As[0][a_c + 3][a_r + 64] = pa1.w;
    *(float4*)&Bs[0][b_r][b_c]     = pb0;
    *(float4*)&Bs[0][b_r + 8][b_c] = pb1;
    __syncthreads();

    const int nk = Kd >> 4;
    for (int t = 0; t < nk; t++) {
        const int cur = t & 1;
        if (t + 1 < nk) {
            const int ko = (t + 1) << 4;
            pa0 = *(const float4*)(Ap0 + ko);
            pa1 = *(const float4*)(Ap1 + ko);
            pb0 = *(const float4*)(Bp0 + (size_t)ko * Nd);
            pb1 = *(const float4*)(Bp1 + (size_t)ko * Nd);
        }
        #pragma unroll
        for (int k = 0; k < 16; k++) {
            float ar[8], br[8];
            *(float4*)&ar[0] = *(const float4*)&As[cur][k][ty << 2];
            *(float4*)&ar[4] = *(const float4*)&As[cur][k][64 + (ty << 2)];
            *(float4*)&br[0] = *(const float4*)&Bs[cur][k][tx << 2];
            *(float4*)&br[4] = *(const float4*)&Bs[cur][k][64 + (tx << 2)];
            #pragma unroll
            for (int i = 0; i < 8; i++)
                #pragma unroll
                for (int j = 0; j < 8; j++)
                    acc[i][j] += ar[i] * br[j];
        }
        if (t + 1 < nk) {
            const int nxt = cur ^ 1;
            As[nxt][a_c + 0][a_r] = pa0.x; As[nxt][a_c + 1][a_r] = pa0.y;
            As[nxt][a_c + 2][a_r] = pa0.z; As[nxt][a_c + 3][a_r] = pa0.w;
            As[nxt][a_c + 0][a_r + 64] = pa1.x; As[nxt][a_c + 1][a_r + 64] = pa1.y;
            As[nxt][a_c + 2][a_r + 64] = pa1.z; As[nxt][a_c + 3][a_r + 64] = pa1.w;
            *(float4*)&Bs[nxt][b_r][b_c]     = pb0;
            *(float4*)&Bs[nxt][b_r + 8][b_c] = pb1;
        }
        __syncthreads();
    }

    // epilogue
    const int col0 = colBase + (tx << 2);
    const int col1 = col0 + 64;
    float bi0[4] = {0.f, 0.f, 0.f, 0.f}, bi1[4] = {0.f, 0.f, 0.f, 0.f};
    if (bias) {
        #pragma unroll
        for (int j = 0; j < 4; j++) { bi0[j] = bias[col0 + j]; bi1[j] = bias[col1 + j]; }
    }
    #pragma unroll
    for (int half = 0; half < 2; half++) {
        const int rbase = rowBase + (ty << 2) + half * 64;
        #pragma unroll
        for (int i = 0; i < 4; i++) {
            const int ia = half * 4 + i;
            float4 o0, o1;
            o0.x = acc[ia][0] + bi0[0]; o0.y = acc[ia][1] + bi0[1];
            o0.z = acc[ia][2] + bi0[2]; o0.w = acc[ia][3] + bi0[3];
            o1.x = acc[ia][4] + bi1[0]; o1.y = acc[ia][5] + bi1[1];
            o1.z = acc[ia][6] + bi1[2]; o1.w = acc[ia][7] + bi1[3];
            if (GELU) {
                o0.x = gelu_exact(o0.x); o0.y = gelu_exact(o0.y);
                o0.z = gelu_exact(o0.z); o0.w = gelu_exact(o0.w);
                o1.x = gelu_exact(o1.x); o1.y = gelu_exact(o1.y);
                o1.z = gelu_exact(o1.z); o1.w = gelu_exact(o1.w);
            }
            float* cp = C + (size_t)(rbase + i) * Nd;
            *(float4*)(cp + col0) = o0;
            *(float4*)(cp + col1) = o1;
        }
    }
}

// ---------------- QKV stage 2: Q/K/V[b,h,m,:] = T[bm, base+h*32+:] @ Vw[h] + bw[h] ----------------
__global__ __launch_bounds__(256)
void qkv2_kernel(const float* __restrict__ T,
                 const float* __restrict__ Vq, const float* __restrict__ Vk, const float* __restrict__ Vv,
                 const float* __restrict__ bq, const float* __restrict__ bk, const float* __restrict__ bv,
                 float* __restrict__ Q, float* __restrict__ K, float* __restrict__ V) {
    __shared__ float Ts[HH*RR];   // 384
    const int bm = blockIdx.x;
    const int which = blockIdx.y;
    const float* Vw = (which == 0) ? Vq : (which == 1) ? Vk : Vv;
    const float* bw = (which == 0) ? bq : (which == 1) ? bk : bv;
    float* O = (which == 0) ? Q : (which == 1) ? K : V;

    for (int i = threadIdx.x; i < HH*RR; i += 256)
        Ts[i] = T[(size_t)bm * NCAT + which * (HH*RR) + i];
    __syncthreads();

    const int b = bm / MM;
    const int m = bm - b * MM;
    for (int o = threadIdx.x; o < HH * DHD; o += 256) {
        int h = o >> 6;
        int d = o & 63;
        float acc = bw[h * DHD + d];
        const float* w = Vw + (size_t)h * (RR * DHD) + d;
        const float* ts = Ts + h * RR;
        #pragma unroll
        for (int r = 0; r < RR; r++)
            acc += ts[r] * w[r * DHD];
        O[(((size_t)b * HH + h) * MM + m) * DHD + d] = acc;
    }
}

// ---------------- flash attention: 4 threads per query row (16 dims each) ----------------
#define FA_T    128
#define FA_ROWS 32          // query rows per CTA (128 threads / 4)
#define FA_BN   32          // KV tile
__global__ __launch_bounds__(FA_T, 4)
void flash_kernel(const float* __restrict__ Q, const float* __restrict__ K,
                  const float* __restrict__ V, const float* __restrict__ mask,
                  float* __restrict__ out) {
    __shared__ float Ks[FA_BN][DHD];
    __shared__ float Vs[FA_BN][DHD];
    __shared__ float Mk[FA_BN];

    const int bh = blockIdx.y;
    const int b  = bh / HH;
    const int h  = bh - b * HH;
    const int t  = threadIdx.x;
    const int quad = t & 3;             // which 16-dim slice
    const int m  = blockIdx.x * FA_ROWS + (t >> 2);
    const int d0 = quad << 4;           // 0,16,32,48

    const float* Qp = Q + ((size_t)bh * MM + m) * DHD + d0;
    float q[16];
    #pragma unroll
    for (int d = 0; d < 16; d += 4) {
        float4 v4 = *(const float4*)(Qp + d);
        q[d] = v4.x; q[d+1] = v4.y; q[d+2] = v4.z; q[d+3] = v4.w;
    }

    float o[16];
    #pragma unroll
    for (int d = 0; d < 16; d++) o[d] = 0.0f;
    float mmax = -1e30f, lsum = 0.0f;

    for (int nb = 0; nb < MM / FA_BN; nb++) {
        const float* Kp = K + ((size_t)bh * MM + nb * FA_BN) * DHD;
        const float* Vp = V + ((size_t)bh * MM + nb * FA_BN) * DHD;
        #pragma unroll
        for (int c = 0; c < FA_BN * DHD / 4 / FA_T; c++) {
            ((float4*)&Ks[0][0])[t + c * FA_T] = ((const float4*)Kp)[t + c * FA_T];
            ((float4*)&Vs[0][0])[t + c * FA_T] = ((const float4*)Vp)[t + c * FA_T];
        }
        if (t < FA_BN)
            Mk[t] = mask[(size_t)b * MM + nb * FA_BN + t];
        __syncthreads();

        float s[FA_BN];
        float bmax = -1e30f;
        #pragma unroll
        for (int j = 0; j < FA_BN; j++) {
            float a0 = 0.f, a1 = 0.f, a2 = 0.f, a3 = 0.f;
            #pragma unroll
            for (int d = 0; d < 16; d += 4) {
                float4 kv = *(const float4*)&Ks[j][d0 + d];
                a0 += q[d]   * kv.x;
                a1 += q[d+1] * kv.y;
                a2 += q[d+2] * kv.z;
                a3 += q[d+3] * kv.w;
            }
            float p = (a0 + a1) + (a2 + a3);
            p += __shfl_xor_sync(0xffffffffu, p, 1);
            p += __shfl_xor_sync(0xffffffffu, p, 2);
            float sv = p * 0.125f + Mk[j];
            s[j] = sv;
            bmax = fmaxf(bmax, sv);
        }
        float mnew = fmaxf(mmax, bmax);
        float corr = __expf(mmax - mnew);
        lsum *= corr;
        #pragma unroll
        for (int d = 0; d < 16; d++) o[d] *= corr;
        #pragma unroll
        for (int j = 0; j < FA_BN; j++) {
            float p = __expf(s[j] - mnew);
            lsum += p;
            #pragma unroll
            for (int d = 0; d < 16; d += 4) {
                float4 vv = *(const float4*)&Vs[j][d0 + d];
                o[d]   += p * vv.x;
                o[d+1] += p * vv.y;
                o[d+2] += p * vv.z;
                o[d+3] += p * vv.w;
            }
        }
        mmax = mnew;
        __syncthreads();
    }

    float inv = 1.0f / lsum;
    float* op = out + ((size_t)b * MM + m) * DM + h * DHD + d0;
    #pragma unroll
    for (int d = 0; d < 16; d += 4) {
        float4 v4;
        v4.x = o[d]   * inv;
        v4.y = o[d+1] * inv;
        v4.z = o[d+2] * inv;
        v4.w = o[d+3] * inv;
        *(float4*)(op + d) = v4;
    }
}

// ---------------- LayerNorm(xa + xb) * g + b, over 768 ----------------
__global__ __launch_bounds__(256)
void ln_kernel(const float* __restrict__ xa, const float* __restrict__ xb,
               const float* __restrict__ gw, const float* __restrict__ bw,
               float* __restrict__ out) {
    const int row = blockIdx.x;
    const int t = threadIdx.x;
    const float* pa = xa + (size_t)row * DM;
    const float* pb = xb + (size_t)row * DM;

    float v0 = pa[t]       + pb[t];
    float v1 = pa[t + 256] + pb[t + 256];
    float v2 = pa[t + 512] + pb[t + 512];

    float s  = v0 + v1 + v2;
    float ss = v0 * v0 + v1 * v1 + v2 * v2;
    #pragma unroll
    for (int off = 16; off > 0; off >>= 1) {
        s  += __shfl_xor_sync(0xffffffffu, s,  off);
        ss += __shfl_xor_sync(0xffffffffu, ss, off);
    }
    __shared__ float wsum[8], wsq[8], stats[2];
    int warp = t >> 5;
    if ((t & 31) == 0) { wsum[warp] = s; wsq[warp] = ss; }
    __syncthreads();
    if (t == 0) {
        float S = 0.f, SS = 0.f;
        #pragma unroll
        for (int w = 0; w < 8; w++) { S += wsum[w]; SS += wsq[w]; }
        float mu = S * (1.0f / DM);
        float var = SS * (1.0f / DM) - mu * mu;
        stats[0] = mu;
        stats[1] = rsqrtf(var + 1e-12f);
    }
    __syncthreads();
    float mu = stats[0], rstd = stats[1];
    float* po = out + (size_t)row * DM;
    po[t]       = (v0 - mu) * rstd * gw[t]       + bw[t];
    po[t + 256] = (v1 - mu) * rstd * gw[t + 256] + bw[t + 256];
    po[t + 512] = (v2 - mu) * rstd * gw[t + 512] + bw[t + 512];
}

// ---------------- launch ----------------
extern "C" void kernel_launch(void* const* d_in, const int* in_sizes, int n_in,
                              void* d_out, int out_size) {
    const float* x    = (const float*)d_in[0];
    const float* mask = (const float*)d_in[1];
    const float* Pq   = (const float*)d_in[2];
    const float* Vq   = (const float*)d_in[3];
    const float* bq   = (const float*)d_in[4];
    const float* Pk   = (const float*)d_in[5];
    const float* Vk   = (const float*)d_in[6];
    const float* bk   = (const float*)d_in[7];
    const float* Pv   = (const float*)d_in[8];
    const float* Vv   = (const float*)d_in[9];
    const float* bv   = (const float*)d_in[10];
    const float* Uo   = (const float*)d_in[11];
    const float* Vo   = (const float*)d_in[12];
    const float* bo   = (const float*)d_in[13];
    const float* U1   = (const float*)d_in[14];
    const float* V1   = (const float*)d_in[15];
    const float* b1   = (const float*)d_in[16];
    const float* U2   = (const float*)d_in[17];
    const float* V2   = (const float*)d_in[18];
    const float* b2   = (const float*)d_in[19];
    const float* ln1g = (const float*)d_in[20];
    const float* ln1b = (const float*)d_in[21];
    const float* ln2g = (const float*)d_in[22];
    const float* ln2b = (const float*)d_in[23];

    float *pPt, *pT, *pQ, *pK, *pV, *pA, *pMid, *pTmp, *pX1, *pH;
    cudaGetSymbolAddress((void**)&pPt,  g_Pt);
    cudaGetSymbolAddress((void**)&pT,   g_T);
    cudaGetSymbolAddress((void**)&pQ,   g_Q);
    cudaGetSymbolAddress((void**)&pK,   g_K);
    cudaGetSymbolAddress((void**)&pV,   g_V);
    cudaGetSymbolAddress((void**)&pA,   g_attn);
    cudaGetSymbolAddress((void**)&pMid, g_mid);
    cudaGetSymbolAddress((void**)&pTmp, g_tmp);
    cudaGetSymbolAddress((void**)&pX1,  g_x1);
    cudaGetSymbolAddress((void**)&pH,   g_hdn);

    // 1) permute P and stage-1 low-rank projection: T = x @ Pt  [8192, 1152]
    permuteP_kernel<<<(DM * NCAT + 255) / 256, 256>>>(Pq, Pk, Pv, pPt);
    sgemm128_kernel<false><<<dim3(NCAT / 128, BMTOT / 128), 256>>>(x, pPt, nullptr, pT, BMTOT, NCAT, DM);

    // 2) stage-2: Q/K/V = T @ V{q,k,v} + b  -> [B,H,M,DH]
    qkv2_kernel<<<dim3(BMTOT, 3), 256>>>(pT, Vq, Vk, Vv, bq, bk, bv, pQ, pK, pV);

    // 3) flash attention -> attn [B,M,H*DH]
    flash_kernel<<<dim3(MM / FA_ROWS, BB * HH), FA_T>>>(pQ, pK, pV, mask, pA);

    // 4) Wo low-rank + bias, then LN1(x + .)
    sgemm128_kernel<false><<<dim3(RFF / 128, BMTOT / 128), 256>>>(pA, Uo, nullptr, pMid, BMTOT, RFF, DM);
    sgemm128_kernel<false><<<dim3(DM / 128, BMTOT / 128), 256>>>(pMid, Vo, bo, pTmp, BMTOT, DM, RFF);
    ln_kernel<<<BMTOT, 256>>>(x, pTmp, ln1g, ln1b, pX1);

    // 5) FFN: mid = x1@U1; hdn = gelu(mid@V1 + b1); mid = hdn@U2; y = mid@V2 + b2; LN2(x1 + y)
    sgemm128_kernel<false><<<dim3(RFF / 128, BMTOT / 128), 256>>>(pX1, U1, nullptr, pMid, BMTOT, RFF, DM);
    sgemm128_kernel<true ><<<dim3(DFF / 128, BMTOT / 128), 256>>>(pMid, V1, b1, pH, BMTOT, DFF, RFF);
    sgemm128_kernel<false><<<dim3(RFF / 128, BMTOT / 128), 256>>>(pH, U2, nullptr, pMid, BMTOT, RFF, DFF);
    sgemm128_kernel<false><<<dim3(DM / 128, BMTOT / 128), 256>>>(pMid, V2, b2, pTmp, BMTOT, DM, RFF);
    ln_kernel<<<BMTOT, 256>>>(pX1, pTmp, ln2g, ln2b, (float*)d_out);
}

// round 10
// speedup vs baseline: 1.9784x; 1.9784x over previous
#include <cuda_runtime.h>
#include <cuda_bf16.h>
#include <math.h>
#include <stdint.h>

// ---------------- problem constants ----------------
#define BB    8
#define MM    1024
#define DM    768
#define HH    12
#define DHD   64
#define RR    32
#define RFF   384
#define DFF   3072
#define BMTOT (BB*MM)          // 8192
#define NCAT  (3*HH*RR)        // 1152

typedef __nv_bfloat16 bf16;
typedef __nv_bfloat162 bf162;

// ---------------- scratch (device globals; no allocs allowed) ----------------
__device__ float g_T   [BMTOT* NCAT];     // x @ Pt (input to qkv2)
__device__ float g_Q   [BMTOT* DM];       // [B,H,M,DH]
__device__ float g_K   [BMTOT* DM];
__device__ float g_V   [BMTOT* DM];
__device__ float g_tmp [BMTOT* DM];
__device__ float g_x1  [BMTOT* DM];
// bf16 split activation buffers
__device__ bf16 g_xs_hi [BMTOT*DM],  g_xs_lo [BMTOT*DM];
__device__ bf16 g_as_hi [BMTOT*DM],  g_as_lo [BMTOT*DM];     // attn
__device__ bf16 g_ms_hi [BMTOT*RFF], g_ms_lo [BMTOT*RFF];    // rank-384 intermediate
__device__ bf16 g_x1s_hi[BMTOT*DM],  g_x1s_lo[BMTOT*DM];
__device__ bf16 g_hs_hi [BMTOT*DFF], g_hs_lo [BMTOT*DFF];    // hdn
// bf16 split transposed weights ([N,K] K-major, B operand)
__device__ bf16 g_ptT_hi[NCAT*DM],  g_ptT_lo[NCAT*DM];       // [1152,768]
__device__ bf16 g_uoT_hi[RFF*DM],   g_uoT_lo[RFF*DM];        // [384,768]
__device__ bf16 g_voT_hi[DM*RFF],   g_voT_lo[DM*RFF];        // [768,384]
__device__ bf16 g_u1T_hi[RFF*DM],   g_u1T_lo[RFF*DM];        // [384,768]
__device__ bf16 g_v1T_hi[DFF*RFF],  g_v1T_lo[DFF*RFF];       // [3072,384]
__device__ bf16 g_u2T_hi[RFF*DFF],  g_u2T_lo[RFF*DFF];       // [384,3072]
__device__ bf16 g_v2T_hi[DM*RFF],   g_v2T_lo[DM*RFF];        // [768,384]

// ---------------- helpers ----------------
__device__ __forceinline__ float gelu_exact(float v) {
    return 0.5f * v * (1.0f + erff(v * 0.70710678118654752440f));
}

__device__ __forceinline__ void split2(float v, bf16& h, bf16& l) {
    h = __float2bfloat16(v);
    l = __float2bfloat16(v - __bfloat162float(h));
}

__device__ __forceinline__ uint32_t smem_u32(const void* p) {
    uint32_t a;
    asm("{ .reg .u64 t; cvta.to.shared.u64 t, %1; cvt.u32.u64 %0, t; }" : "=r"(a) : "l"(p));
    return a;
}

__device__ __forceinline__ void ldsm4(uint32_t* r, uint32_t addr) {
    asm volatile("ldmatrix.sync.aligned.m8n8.x4.shared.b16 {%0,%1,%2,%3}, [%4];"
                 : "=r"(r[0]), "=r"(r[1]), "=r"(r[2]), "=r"(r[3]) : "r"(addr));
}

__device__ __forceinline__ void mma16816(float* d, const uint32_t* a, const uint32_t* b) {
    asm volatile(
        "mma.sync.aligned.m16n8k16.row.col.f32.bf16.bf16.f32 "
        "{%0,%1,%2,%3}, {%4,%5,%6,%7}, {%8,%9}, {%0,%1,%2,%3};"
        : "+f"(d[0]), "+f"(d[1]), "+f"(d[2]), "+f"(d[3])
        : "r"(a[0]), "r"(a[1]), "r"(a[2]), "r"(a[3]), "r"(b[0]), "r"(b[1]));
}

// ---------------- conversion kernels ----------------
__global__ void split_act_kernel(const float* __restrict__ A, bf16* __restrict__ hi,
                                 bf16* __restrict__ lo, int n4) {
    int i = blockIdx.x * 256 + threadIdx.x;
    if (i >= n4) return;
    float4 v = ((const float4*)A)[i];
    bf16 h0, l0, h1, l1, h2, l2, h3, l3;
    split2(v.x, h0, l0); split2(v.y, h1, l1); split2(v.z, h2, l2); split2(v.w, h3, l3);
    bf162* ph = (bf162*)(hi + (size_t)i * 4);
    bf162* pl = (bf162*)(lo + (size_t)i * 4);
    ph[0] = bf162(h0, h1); ph[1] = bf162(h2, h3);
    pl[0] = bf162(l0, l1); pl[1] = bf162(l2, l3);
}

// transpose+split weight: W[K,N] fp32 -> out[N,K] bf16 hi/lo
__global__ void splitWT_kernel(const float* __restrict__ W, bf16* __restrict__ hiT,
                               bf16* __restrict__ loT, int K, int N) {
    int i = blockIdx.x * 256 + threadIdx.x;
    if (i >= K * N) return;
    int n = i / K;
    int k = i - n * K;
    bf16 h, l;
    split2(W[(size_t)k * N + n], h, l);
    hiT[i] = h; loT[i] = l;
}

// P permute+split: [H,DM,R] x3 -> PtT [3*H*R, DM] bf16 hi/lo
__global__ void permutePtT_kernel(const float* __restrict__ Pq, const float* __restrict__ Pk,
                                  const float* __restrict__ Pv,
                                  bf16* __restrict__ hiT, bf16* __restrict__ loT) {
    int idx = blockIdx.x * 256 + threadIdx.x;
    if (idx >= NCAT * DM) return;
    int n = idx / DM;
    int d = idx - n * DM;
    int which = n / (HH*RR);
    int hn = n - which * (HH*RR);
    int h = hn >> 5;
    int r = hn & 31;
    const float* P = (which == 0) ? Pq : (which == 1) ? Pk : Pv;
    bf16 hh, ll;
    split2(P[((size_t)h * DM + d) * RR + r], hh, ll);
    hiT[idx] = hh; loT[idx] = ll;
}

// ---------------- mma.sync split-bf16 GEMM ----------------
// C[M,N] = A[M,K] @ B^T, B stored [N,K] K-major, hi/lo split, fp32 reg accum.
// CTA tile 128x128, K chunk 64, 8 warps (warp tile 32Mx64N).
#define KC 64
#define SMEM_GEMM (4 * 128 * KC * 2)   // 65536 bytes

__global__ __launch_bounds__(256)
void mma_gemm_kernel(const bf16* __restrict__ Ahi, const bf16* __restrict__ Alo,
                     const bf16* __restrict__ Bhi, const bf16* __restrict__ Blo,
                     const float* __restrict__ bias,
                     float* __restrict__ Cf, bf16* __restrict__ Chi, bf16* __restrict__ Clo,
                     int Md, int Nd, int Kd, int doGelu) {
    extern __shared__ char smraw[];
    bf16* sAhi = (bf16*)smraw;                 // [128][64] swizzled
    bf16* sAlo = sAhi + 128 * KC;
    bf16* sBhi = sAlo + 128 * KC;
    bf16* sBlo = sBhi + 128 * KC;
    const uint32_t uAhi = smem_u32(sAhi);
    const uint32_t uAlo = smem_u32(sAlo);
    const uint32_t uBhi = smem_u32(sBhi);
    const uint32_t uBlo = smem_u32(sBlo);

    const int tid  = threadIdx.x;
    const int wid  = tid >> 5;
    const int lane = tid & 31;
    const int warpM = wid & 3;     // 4 warps over M (32 rows each)
    const int warpN = wid >> 2;    // 2 warps over N (64 cols each)
    const int rowBase = blockIdx.y * 128;
    const int colBase = blockIdx.x * 128;

    // gmem->smem mapping: thread -> row = tid>>1 (0..127), 4 x 16B chunks
    const int lrow  = tid >> 1;
    const int lseg0 = (tid & 1) * 4;

    float acc[2][8][4];
    #pragma unroll
    for (int i = 0; i < 2; i++)
        #pragma unroll
        for (int j = 0; j < 8; j++)
            #pragma unroll
            for (int e = 0; e < 4; e++) acc[i][j][e] = 0.0f;

    // precomputed ldmatrix offsets (bytes within a tile)
    const int arow0 = warpM * 32 + (lane & 15);      // + i*16
    const int alsel = lane >> 4;                     // chunk低bit
    const int brow0 = warpN * 64 + (lane & 7) + ((lane >> 4) << 3);  // + g*16
    const int bcsel = (lane >> 3) & 1;

    const int nChunks = Kd / KC;
    for (int c = 0; c < nChunks; c++) {
        const int k0 = c * KC;
        // load 4 tiles
        {
            const bf16* pa = Ahi + (size_t)(rowBase + lrow) * Kd + k0 + lseg0 * 8;
            const bf16* pl = Alo + (size_t)(rowBase + lrow) * Kd + k0 + lseg0 * 8;
            const bf16* pb = Bhi + (size_t)(colBase + lrow) * Kd + k0 + lseg0 * 8;
            const bf16* pc = Blo + (size_t)(colBase + lrow) * Kd + k0 + lseg0 * 8;
            #pragma unroll
            for (int s = 0; s < 4; s++) {
                const int cc = lseg0 + s;
                const uint32_t off = (uint32_t)lrow * KC + (uint32_t)((cc ^ (lrow & 7)) * 8);
                *(uint4*)(sAhi + off) = *(const uint4*)(pa + s * 8);
                *(uint4*)(sAlo + off) = *(const uint4*)(pl + s * 8);
                *(uint4*)(sBhi + off) = *(const uint4*)(pb + s * 8);
                *(uint4*)(sBlo + off) = *(const uint4*)(pc + s * 8);
            }
        }
        __syncthreads();

        #pragma unroll
        for (int step = 0; step < 4; step++) {
            uint32_t ah[2][4], al[2][4], bh[16], bl[16];
            // A frags (i = 0,1)
            #pragma unroll
            for (int i = 0; i < 2; i++) {
                const int ar = arow0 + i * 16;
                const int cc = step * 2 + alsel;
                const uint32_t off = (uint32_t)(ar * 128 + ((cc ^ (ar & 7)) << 4));
                ldsm4(ah[i], uAhi + off);
                ldsm4(al[i], uAlo + off);
            }
            // B frags (g = 0..3, each covers n-frags 2g, 2g+1)
            #pragma unroll
            for (int g = 0; g < 4; g++) {
                const int br = brow0 + g * 16;
                const int cc = step * 2 + bcsel;
                const uint32_t off = (uint32_t)(br * 128 + ((cc ^ (br & 7)) << 4));
                ldsm4(&bh[g * 4], uBhi + off);
                ldsm4(&bl[g * 4], uBlo + off);
            }
            #pragma unroll
            for (int i = 0; i < 2; i++)
                #pragma unroll
                for (int j = 0; j < 8; j++) {
                    mma16816(acc[i][j], ah[i], &bh[j * 2]);
                    mma16816(acc[i][j], ah[i], &bl[j * 2]);
                    mma16816(acc[i][j], al[i], &bh[j * 2]);
                }
        }
        __syncthreads();
    }

    // epilogue: direct register -> gmem
    const int mrowW = rowBase + warpM * 32;
    const int ncolW = colBase + warpN * 64;
    #pragma unroll
    for (int i = 0; i < 2; i++) {
        const int r0 = mrowW + i * 16 + (lane >> 2);
        const int r1 = r0 + 8;
        #pragma unroll
        for (int j = 0; j < 8; j++) {
            const int col = ncolW + j * 8 + (lane & 3) * 2;
            float v0 = acc[i][j][0], v1 = acc[i][j][1];   // row r0
            float v2 = acc[i][j][2], v3 = acc[i][j][3];   // row r1
            if (bias) {
                const float b0 = bias[col], b1 = bias[col + 1];
                v0 += b0; v1 += b1; v2 += b0; v3 += b1;
            }
            if (doGelu) {
                v0 = gelu_exact(v0); v1 = gelu_exact(v1);
                v2 = gelu_exact(v2); v3 = gelu_exact(v3);
            }
            if (Cf) {
                *(float2*)(Cf + (size_t)r0 * Nd + col) = make_float2(v0, v1);
                *(float2*)(Cf + (size_t)r1 * Nd + col) = make_float2(v2, v3);
            }
            if (Chi) {
                bf16 h0,l0,h1,l1;
                split2(v0, h0, l0); split2(v1, h1, l1);
                *(bf162*)(Chi + (size_t)r0 * Nd + col) = bf162(h0, h1);
                *(bf162*)(Clo + (size_t)r0 * Nd + col) = bf162(l0, l1);
                split2(v2, h0, l0); split2(v3, h1, l1);
                *(bf162*)(Chi + (size_t)r1 * Nd + col) = bf162(h0, h1);
                *(bf162*)(Clo + (size_t)r1 * Nd + col) = bf162(l0, l1);
            }
        }
    }
}

// ---------------- QKV stage 2 (fp32, reads g_T) ----------------
__global__ __launch_bounds__(256)
void qkv2_kernel(const float* __restrict__ T,
                 const float* __restrict__ Vq, const float* __restrict__ Vk, const float* __restrict__ Vv,
                 const float* __restrict__ bq, const float* __restrict__ bk, const float* __restrict__ bv,
                 float* __restrict__ Q, float* __restrict__ K, float* __restrict__ V) {
    __shared__ float Ts[HH*RR];
    const int bm = blockIdx.x;
    const int which = blockIdx.y;
    const float* Vw = (which == 0) ? Vq : (which == 1) ? Vk : Vv;
    const float* bw = (which == 0) ? bq : (which == 1) ? bk : bv;
    float* O = (which == 0) ? Q : (which == 1) ? K : V;

    for (int i = threadIdx.x; i < HH*RR; i += 256)
        Ts[i] = T[(size_t)bm * NCAT + which * (HH*RR) + i];
    __syncthreads();

    const int b = bm / MM;
    const int m = bm - b * MM;
    for (int o = threadIdx.x; o < HH * DHD; o += 256) {
        int h = o >> 6;
        int d = o & 63;
        float acc = bw[h * DHD + d];
        const float* w = Vw + (size_t)h * (RR * DHD) + d;
        const float* ts = Ts + h * RR;
        #pragma unroll
        for (int r = 0; r < RR; r++)
            acc += ts[r] * w[r * DHD];
        O[(((size_t)b * HH + h) * MM + m) * DHD + d] = acc;
    }
}

// ---------------- flash attention (1 thread = 1 query row), split bf16 output ----------------
#define FA_BM 128
#define FA_BN 32
__global__ __launch_bounds__(FA_BM)
void flash_kernel(const float* __restrict__ Q, const float* __restrict__ K,
                  const float* __restrict__ V, const float* __restrict__ mask,
                  bf16* __restrict__ out_hi, bf16* __restrict__ out_lo) {
    __shared__ float Ks[FA_BN][DHD];
    __shared__ float Vs[FA_BN][DHD];
    __shared__ float Mk[FA_BN];

    const int bh = blockIdx.y;
    const int b  = bh / HH;
    const int h  = bh - b * HH;
    const int m  = blockIdx.x * FA_BM + threadIdx.x;

    const float* Qp = Q + ((size_t)bh * MM + m) * DHD;
    float q[DHD];
    #pragma unroll
    for (int d = 0; d < DHD; d += 4) {
        float4 v4 = *(const float4*)(Qp + d);
        q[d] = v4.x; q[d+1] = v4.y; q[d+2] = v4.z; q[d+3] = v4.w;
    }

    float o[DHD];
    #pragma unroll
    for (int d = 0; d < DHD; d++) o[d] = 0.0f;
    float mmax = -1e30f, lsum = 0.0f;

    for (int nb = 0; nb < MM / FA_BN; nb++) {
        const float* Kp = K + ((size_t)bh * MM + nb * FA_BN) * DHD;
        const float* Vp = V + ((size_t)bh * MM + nb * FA_BN) * DHD;
        for (int i = threadIdx.x; i < FA_BN * DHD / 4; i += FA_BM) {
            ((float4*)&Ks[0][0])[i] = ((const float4*)Kp)[i];
            ((float4*)&Vs[0][0])[i] = ((const float4*)Vp)[i];
        }
        if (threadIdx.x < FA_BN)
            Mk[threadIdx.x] = mask[(size_t)b * MM + nb * FA_BN + threadIdx.x];
        __syncthreads();

        float s[FA_BN];
        float bmax = -1e30f;
        #pragma unroll
        for (int j = 0; j < FA_BN; j++) {
            float a0 = 0.f, a1 = 0.f, a2 = 0.f, a3 = 0.f;
            #pragma unroll
            for (int d = 0; d < DHD; d += 4) {
                float4 kv = *(const float4*)&Ks[j][d];
                a0 += q[d]   * kv.x;
                a1 += q[d+1] * kv.y;
                a2 += q[d+2] * kv.z;
                a3 += q[d+3] * kv.w;
            }
            float sv = (a0 + a1 + a2 + a3) * 0.125f + Mk[j];
            s[j] = sv;
            bmax = fmaxf(bmax, sv);
        }
        float mnew = fmaxf(mmax, bmax);
        float corr = __expf(mmax - mnew);
        lsum *= corr;
        #pragma unroll
        for (int d = 0; d < DHD; d++) o[d] *= corr;
        #pragma unroll
        for (int j = 0; j < FA_BN; j++) {
            float p = __expf(s[j] - mnew);
            lsum += p;
            #pragma unroll
            for (int d = 0; d < DHD; d += 4) {
                float4 vv = *(const float4*)&Vs[j][d];
                o[d]   += p * vv.x;
                o[d+1] += p * vv.y;
                o[d+2] += p * vv.z;
                o[d+3] += p * vv.w;
            }
        }
        mmax = mnew;
        __syncthreads();
    }

    float inv = 1.0f / lsum;
    const size_t base = ((size_t)b * MM + m) * DM + h * DHD;
    #pragma unroll
    for (int d = 0; d < DHD; d += 2) {
        bf16 h0, l0, h1, l1;
        split2(o[d]   * inv, h0, l0);
        split2(o[d+1] * inv, h1, l1);
        *(bf162*)(out_hi + base + d) = bf162(h0, h1);
        *(bf162*)(out_lo + base + d) = bf162(l0, l1);
    }
}

// ---------------- LayerNorm(xa + xb) * g + b, over 768; optional split output ----------------
__global__ __launch_bounds__(256)
void ln_kernel(const float* __restrict__ xa, const float* __restrict__ xb,
               const float* __restrict__ gw, const float* __restrict__ bw,
               float* __restrict__ out, bf16* __restrict__ ohi, bf16* __restrict__ olo) {
    const int row = blockIdx.x;
    const int t = threadIdx.x;
    const float* pa = xa + (size_t)row * DM;
    const float* pb = xb + (size_t)row * DM;

    float v0 = pa[t]       + pb[t];
    float v1 = pa[t + 256] + pb[t + 256];
    float v2 = pa[t + 512] + pb[t + 512];

    float s  = v0 + v1 + v2;
    float ss = v0 * v0 + v1 * v1 + v2 * v2;
    #pragma unroll
    for (int off = 16; off > 0; off >>= 1) {
        s  += __shfl_xor_sync(0xffffffffu, s,  off);
        ss += __shfl_xor_sync(0xffffffffu, ss, off);
    }
    __shared__ float wsum[8], wsq[8], stats[2];
    int warp = t >> 5;
    if ((t & 31) == 0) { wsum[warp] = s; wsq[warp] = ss; }
    __syncthreads();
    if (t == 0) {
        float S = 0.f, SS = 0.f;
        #pragma unroll
        for (int w = 0; w < 8; w++) { S += wsum[w]; SS += wsq[w]; }
        float mu = S * (1.0f / DM);
        float var = SS * (1.0f / DM) - mu * mu;
        stats[0] = mu;
        stats[1] = rsqrtf(var + 1e-12f);
    }
    __syncthreads();
    float mu = stats[0], rstd = stats[1];
    float* po = out + (size_t)row * DM;
    float r0 = (v0 - mu) * rstd * gw[t]       + bw[t];
    float r1 = (v1 - mu) * rstd * gw[t + 256] + bw[t + 256];
    float r2 = (v2 - mu) * rstd * gw[t + 512] + bw[t + 512];
    po[t] = r0; po[t + 256] = r1; po[t + 512] = r2;
    if (ohi) {
        bf16 hh, ll;
        split2(r0, hh, ll); ohi[(size_t)row*DM + t]       = hh; olo[(size_t)row*DM + t]       = ll;
        split2(r1, hh, ll); ohi[(size_t)row*DM + t + 256] = hh; olo[(size_t)row*DM + t + 256] = ll;
        split2(r2, hh, ll); ohi[(size_t)row*DM + t + 512] = hh; olo[(size_t)row*DM + t + 512] = ll;
    }
}

// ---------------- launch ----------------
static inline void launch_mma(const bf16* Ahi, const bf16* Alo, const bf16* Bhi, const bf16* Blo,
                              const float* bias, float* Cf, bf16* Chi, bf16* Clo,
                              int Md, int Nd, int Kd, int doGelu) {
    dim3 grid(Nd / 128, Md / 128);
    mma_gemm_kernel<<<grid, 256, SMEM_GEMM>>>(Ahi, Alo, Bhi, Blo, bias, Cf, Chi, Clo,
                                              Md, Nd, Kd, doGelu);
}

extern "C" void kernel_launch(void* const* d_in, const int* in_sizes, int n_in,
                              void* d_out, int out_size) {
    const float* x    = (const float*)d_in[0];
    const float* mask = (const float*)d_in[1];
    const float* Pq   = (const float*)d_in[2];
    const float* Vq   = (const float*)d_in[3];
    const float* bq   = (const float*)d_in[4];
    const float* Pk   = (const float*)d_in[5];
    const float* Vk   = (const float*)d_in[6];
    const float* bk   = (const float*)d_in[7];
    const float* Pv   = (const float*)d_in[8];
    const float* Vv   = (const float*)d_in[9];
    const float* bv   = (const float*)d_in[10];
    const float* Uo   = (const float*)d_in[11];
    const float* Vo   = (const float*)d_in[12];
    const float* bo   = (const float*)d_in[13];
    const float* U1   = (const float*)d_in[14];
    const float* V1   = (const float*)d_in[15];
    const float* b1   = (const float*)d_in[16];
    const float* U2   = (const float*)d_in[17];
    const float* V2   = (const float*)d_in[18];
    const float* b2   = (const float*)d_in[19];
    const float* ln1g = (const float*)d_in[20];
    const float* ln1b = (const float*)d_in[21];
    const float* ln2g = (const float*)d_in[22];
    const float* ln2b = (const float*)d_in[23];

    static bool attrSet = false;
    if (!attrSet) {
        cudaFuncSetAttribute(mma_gemm_kernel, cudaFuncAttributeMaxDynamicSharedMemorySize, SMEM_GEMM);
        attrSet = true;
    }

    float *pT, *pQ, *pK, *pV, *pTmp, *pX1;
    cudaGetSymbolAddress((void**)&pT,   g_T);
    cudaGetSymbolAddress((void**)&pQ,   g_Q);
    cudaGetSymbolAddress((void**)&pK,   g_K);
    cudaGetSymbolAddress((void**)&pV,   g_V);
    cudaGetSymbolAddress((void**)&pTmp, g_tmp);
    cudaGetSymbolAddress((void**)&pX1,  g_x1);

    bf16 *xsH,*xsL,*asH,*asL,*msH,*msL,*x1H,*x1L,*hsH,*hsL;
    bf16 *ptH,*ptL,*uoH,*uoL,*voH,*voL,*u1H,*u1L,*v1H,*v1L,*u2H,*u2L,*v2H,*v2L;
    cudaGetSymbolAddress((void**)&xsH, g_xs_hi);  cudaGetSymbolAddress((void**)&xsL, g_xs_lo);
    cudaGetSymbolAddress((void**)&asH, g_as_hi);  cudaGetSymbolAddress((void**)&asL, g_as_lo);
    cudaGetSymbolAddress((void**)&msH, g_ms_hi);  cudaGetSymbolAddress((void**)&msL, g_ms_lo);
    cudaGetSymbolAddress((void**)&x1H, g_x1s_hi); cudaGetSymbolAddress((void**)&x1L, g_x1s_lo);
    cudaGetSymbolAddress((void**)&hsH, g_hs_hi);  cudaGetSymbolAddress((void**)&hsL, g_hs_lo);
    cudaGetSymbolAddress((void**)&ptH, g_ptT_hi); cudaGetSymbolAddress((void**)&ptL, g_ptT_lo);
    cudaGetSymbolAddress((void**)&uoH, g_uoT_hi); cudaGetSymbolAddress((void**)&uoL, g_uoT_lo);
    cudaGetSymbolAddress((void**)&voH, g_voT_hi); cudaGetSymbolAddress((void**)&voL, g_voT_lo);
    cudaGetSymbolAddress((void**)&u1H, g_u1T_hi); cudaGetSymbolAddress((void**)&u1L, g_u1T_lo);
    cudaGetSymbolAddress((void**)&v1H, g_v1T_hi); cudaGetSymbolAddress((void**)&v1L, g_v1T_lo);
    cudaGetSymbolAddress((void**)&u2H, g_u2T_hi); cudaGetSymbolAddress((void**)&u2L, g_u2T_lo);
    cudaGetSymbolAddress((void**)&v2H, g_v2T_hi); cudaGetSymbolAddress((void**)&v2L, g_v2T_lo);

    // ---- weight conversions ----
    permutePtT_kernel<<<(NCAT * DM + 255) / 256, 256>>>(Pq, Pk, Pv, ptH, ptL);
    splitWT_kernel<<<(DM * RFF + 255) / 256, 256>>>(Uo, uoH, uoL, DM, RFF);   // Uo[768,384] -> [384,768]
    splitWT_kernel<<<(RFF * DM + 255) / 256, 256>>>(Vo, voH, voL, RFF, DM);   // Vo[384,768] -> [768,384]
    splitWT_kernel<<<(DM * RFF + 255) / 256, 256>>>(U1, u1H, u1L, DM, RFF);
    splitWT_kernel<<<(RFF * DFF + 255) / 256, 256>>>(V1, v1H, v1L, RFF, DFF); // -> [3072,384]
    splitWT_kernel<<<(DFF * RFF + 255) / 256, 256>>>(U2, u2H, u2L, DFF, RFF); // -> [384,3072]
    splitWT_kernel<<<(RFF * DM + 255) / 256, 256>>>(V2, v2H, v2L, RFF, DM);

    // ---- 1) split x; T = x @ Pt  [8192,1152] fp32 ----
    split_act_kernel<<<(BMTOT * DM / 4 + 255) / 256, 256>>>(x, xsH, xsL, BMTOT * DM / 4);
    launch_mma(xsH, xsL, ptH, ptL, nullptr, pT, nullptr, nullptr, BMTOT, NCAT, DM, 0);

    // ---- 2) QKV stage 2 ----
    qkv2_kernel<<<dim3(BMTOT, 3), 256>>>(pT, Vq, Vk, Vv, bq, bk, bv, pQ, pK, pV);

    // ---- 3) flash attention -> attn split ----
    flash_kernel<<<dim3(MM / FA_BM, BB * HH), FA_BM>>>(pQ, pK, pV, mask, asH, asL);

    // ---- 4) Wo low-rank + LN1 ----
    launch_mma(asH, asL, uoH, uoL, nullptr, nullptr, msH, msL, BMTOT, RFF, DM, 0);
    launch_mma(msH, msL, voH, voL, bo, pTmp, nullptr, nullptr, BMTOT, DM, RFF, 0);
    ln_kernel<<<BMTOT, 256>>>(x, pTmp, ln1g, ln1b, pX1, x1H, x1L);

    // ---- 5) FFN ----
    launch_mma(x1H, x1L, u1H, u1L, nullptr, nullptr, msH, msL, BMTOT, RFF, DM, 0);
    launch_mma(msH, msL, v1H, v1L, b1, nullptr, hsH, hsL, BMTOT, DFF, RFF, 1);
    launch_mma(hsH, hsL, u2H, u2L, nullptr, nullptr, msH, msL, BMTOT, RFF, DFF, 0);
    launch_mma(msH, msL, v2H, v2L, b2, pTmp, nullptr, nullptr, BMTOT, DM, RFF, 0);
    ln_kernel<<<BMTOT, 256>>>(pX1, pTmp, ln2g, ln2b, (float*)d_out, nullptr, nullptr);
}

// round 11
// speedup vs baseline: 2.8933x; 1.4625x over previous
#include <cuda_runtime.h>
#include <cuda_bf16.h>
#include <math.h>
#include <stdint.h>

// ---------------- problem constants ----------------
#define BB    8
#define MM    1024
#define DM    768
#define HH    12
#define DHD   64
#define RR    32
#define RFF   384
#define DFF   3072
#define BMTOT (BB*MM)          // 8192
#define NCAT  (3*HH*RR)        // 1152

typedef __nv_bfloat16 bf16;
typedef __nv_bfloat162 bf162;

// ---------------- scratch (device globals; no allocs allowed) ----------------
__device__ float g_T   [BMTOT* NCAT];     // x @ Pt (input to qkv2)
__device__ float g_Q   [BMTOT* DM];       // reused as split bf16 Qhi|Qlo
__device__ float g_K   [BMTOT* DM];       // reused as split bf16 Khi|Klo
__device__ float g_V   [BMTOT* DM];       // reused as split bf16 Vhi|Vlo
__device__ float g_tmp [BMTOT* DM];
__device__ float g_x1  [BMTOT* DM];
// bf16 split activation buffers
__device__ bf16 g_xs_hi [BMTOT*DM],  g_xs_lo [BMTOT*DM];
__device__ bf16 g_as_hi [BMTOT*DM],  g_as_lo [BMTOT*DM];     // attn
__device__ bf16 g_ms_hi [BMTOT*RFF], g_ms_lo [BMTOT*RFF];    // rank-384 intermediate
__device__ bf16 g_x1s_hi[BMTOT*DM],  g_x1s_lo[BMTOT*DM];
__device__ bf16 g_hs_hi [BMTOT*DFF], g_hs_lo [BMTOT*DFF];    // hdn
// bf16 split transposed weights ([N,K] K-major, B operand)
__device__ bf16 g_ptT_hi[NCAT*DM],  g_ptT_lo[NCAT*DM];
__device__ bf16 g_uoT_hi[RFF*DM],   g_uoT_lo[RFF*DM];
__device__ bf16 g_voT_hi[DM*RFF],   g_voT_lo[DM*RFF];
__device__ bf16 g_u1T_hi[RFF*DM],   g_u1T_lo[RFF*DM];
__device__ bf16 g_v1T_hi[DFF*RFF],  g_v1T_lo[DFF*RFF];
__device__ bf16 g_u2T_hi[RFF*DFF],  g_u2T_lo[RFF*DFF];
__device__ bf16 g_v2T_hi[DM*RFF],   g_v2T_lo[DM*RFF];

// ---------------- helpers ----------------
__device__ __forceinline__ float gelu_exact(float v) {
    return 0.5f * v * (1.0f + erff(v * 0.70710678118654752440f));
}

__device__ __forceinline__ void split2(float v, bf16& h, bf16& l) {
    h = __float2bfloat16(v);
    l = __float2bfloat16(v - __bfloat162float(h));
}

__device__ __forceinline__ uint32_t pack_bf16(float a, float b) {
    bf162 t(__float2bfloat16(a), __float2bfloat16(b));
    return *(uint32_t*)&t;
}
__device__ __forceinline__ void split_pack(float a, float b, uint32_t& hi, uint32_t& lo) {
    bf16 ha, la, hb, lb;
    split2(a, ha, la); split2(b, hb, lb);
    bf162 th(ha, hb), tl(la, lb);
    hi = *(uint32_t*)&th; lo = *(uint32_t*)&tl;
}

__device__ __forceinline__ uint32_t smem_u32(const void* p) {
    uint32_t a;
    asm("{ .reg .u64 t; cvta.to.shared.u64 t, %1; cvt.u32.u64 %0, t; }" : "=r"(a) : "l"(p));
    return a;
}

__device__ __forceinline__ void ldsm4(uint32_t* r, uint32_t addr) {
    asm volatile("ldmatrix.sync.aligned.m8n8.x4.shared.b16 {%0,%1,%2,%3}, [%4];"
                 : "=r"(r[0]), "=r"(r[1]), "=r"(r[2]), "=r"(r[3]) : "r"(addr));
}
__device__ __forceinline__ void ldsm4t(uint32_t* r, uint32_t addr) {
    asm volatile("ldmatrix.sync.aligned.m8n8.x4.trans.shared.b16 {%0,%1,%2,%3}, [%4];"
                 : "=r"(r[0]), "=r"(r[1]), "=r"(r[2]), "=r"(r[3]) : "r"(addr));
}

__device__ __forceinline__ void mma16816(float* d, const uint32_t* a, const uint32_t* b) {
    asm volatile(
        "mma.sync.aligned.m16n8k16.row.col.f32.bf16.bf16.f32 "
        "{%0,%1,%2,%3}, {%4,%5,%6,%7}, {%8,%9}, {%0,%1,%2,%3};"
        : "+f"(d[0]), "+f"(d[1]), "+f"(d[2]), "+f"(d[3])
        : "r"(a[0]), "r"(a[1]), "r"(a[2]), "r"(a[3]), "r"(b[0]), "r"(b[1]));
}

// ---------------- conversion kernels ----------------
__global__ void split_act_kernel(const float* __restrict__ A, bf16* __restrict__ hi,
                                 bf16* __restrict__ lo, int n4) {
    int i = blockIdx.x * 256 + threadIdx.x;
    if (i >= n4) return;
    float4 v = ((const float4*)A)[i];
    bf16 h0, l0, h1, l1, h2, l2, h3, l3;
    split2(v.x, h0, l0); split2(v.y, h1, l1); split2(v.z, h2, l2); split2(v.w, h3, l3);
    bf162* ph = (bf162*)(hi + (size_t)i * 4);
    bf162* pl = (bf162*)(lo + (size_t)i * 4);
    ph[0] = bf162(h0, h1); ph[1] = bf162(h2, h3);
    pl[0] = bf162(l0, l1); pl[1] = bf162(l2, l3);
}

__global__ void splitWT_kernel(const float* __restrict__ W, bf16* __restrict__ hiT,
                               bf16* __restrict__ loT, int K, int N) {
    int i = blockIdx.x * 256 + threadIdx.x;
    if (i >= K * N) return;
    int n = i / K;
    int k = i - n * K;
    bf16 h, l;
    split2(W[(size_t)k * N + n], h, l);
    hiT[i] = h; loT[i] = l;
}

__global__ void permutePtT_kernel(const float* __restrict__ Pq, const float* __restrict__ Pk,
                                  const float* __restrict__ Pv,
                                  bf16* __restrict__ hiT, bf16* __restrict__ loT) {
    int idx = blockIdx.x * 256 + threadIdx.x;
    if (idx >= NCAT * DM) return;
    int n = idx / DM;
    int d = idx - n * DM;
    int which = n / (HH*RR);
    int hn = n - which * (HH*RR);
    int h = hn >> 5;
    int r = hn & 31;
    const float* P = (which == 0) ? Pq : (which == 1) ? Pk : Pv;
    bf16 hh, ll;
    split2(P[((size_t)h * DM + d) * RR + r], hh, ll);
    hiT[idx] = hh; loT[idx] = ll;
}

// ---------------- mma.sync split-bf16 GEMM (unchanged from R10) ----------------
#define KC 64
#define SMEM_GEMM (4 * 128 * KC * 2)   // 65536 bytes

__global__ __launch_bounds__(256)
void mma_gemm_kernel(const bf16* __restrict__ Ahi, const bf16* __restrict__ Alo,
                     const bf16* __restrict__ Bhi, const bf16* __restrict__ Blo,
                     const float* __restrict__ bias,
                     float* __restrict__ Cf, bf16* __restrict__ Chi, bf16* __restrict__ Clo,
                     int Md, int Nd, int Kd, int doGelu) {
    extern __shared__ char smraw[];
    bf16* sAhi = (bf16*)smraw;
    bf16* sAlo = sAhi + 128 * KC;
    bf16* sBhi = sAlo + 128 * KC;
    bf16* sBlo = sBhi + 128 * KC;
    const uint32_t uAhi = smem_u32(sAhi);
    const uint32_t uAlo = smem_u32(sAlo);
    const uint32_t uBhi = smem_u32(sBhi);
    const uint32_t uBlo = smem_u32(sBlo);

    const int tid  = threadIdx.x;
    const int wid  = tid >> 5;
    const int lane = tid & 31;
    const int warpM = wid & 3;
    const int warpN = wid >> 2;
    const int rowBase = blockIdx.y * 128;
    const int colBase = blockIdx.x * 128;

    const int lrow  = tid >> 1;
    const int lseg0 = (tid & 1) * 4;

    float acc[2][8][4];
    #pragma unroll
    for (int i = 0; i < 2; i++)
        #pragma unroll
        for (int j = 0; j < 8; j++)
            #pragma unroll
            for (int e = 0; e < 4; e++) acc[i][j][e] = 0.0f;

    const int arow0 = warpM * 32 + (lane & 15);
    const int alsel = lane >> 4;
    const int brow0 = warpN * 64 + (lane & 7) + ((lane >> 4) << 3);
    const int bcsel = (lane >> 3) & 1;

    const int nChunks = Kd / KC;
    for (int c = 0; c < nChunks; c++) {
        const int k0 = c * KC;
        {
            const bf16* pa = Ahi + (size_t)(rowBase + lrow) * Kd + k0 + lseg0 * 8;
            const bf16* pl = Alo + (size_t)(rowBase + lrow) * Kd + k0 + lseg0 * 8;
            const bf16* pb = Bhi + (size_t)(colBase + lrow) * Kd + k0 + lseg0 * 8;
            const bf16* pc = Blo + (size_t)(colBase + lrow) * Kd + k0 + lseg0 * 8;
            #pragma unroll
            for (int s = 0; s < 4; s++) {
                const int cc = lseg0 + s;
                const uint32_t off = (uint32_t)lrow * KC + (uint32_t)((cc ^ (lrow & 7)) * 8);
                *(uint4*)(sAhi + off) = *(const uint4*)(pa + s * 8);
                *(uint4*)(sAlo + off) = *(const uint4*)(pl + s * 8);
                *(uint4*)(sBhi + off) = *(const uint4*)(pb + s * 8);
                *(uint4*)(sBlo + off) = *(const uint4*)(pc + s * 8);
            }
        }
        __syncthreads();

        #pragma unroll
        for (int step = 0; step < 4; step++) {
            uint32_t ah[2][4], al[2][4], bh[16], bl[16];
            #pragma unroll
            for (int i = 0; i < 2; i++) {
                const int ar = arow0 + i * 16;
                const int cc = step * 2 + alsel;
                const uint32_t off = (uint32_t)(ar * 128 + ((cc ^ (ar & 7)) << 4));
                ldsm4(ah[i], uAhi + off);
                ldsm4(al[i], uAlo + off);
            }
            #pragma unroll
            for (int g = 0; g < 4; g++) {
                const int br = brow0 + g * 16;
                const int cc = step * 2 + bcsel;
                const uint32_t off = (uint32_t)(br * 128 + ((cc ^ (br & 7)) << 4));
                ldsm4(&bh[g * 4], uBhi + off);
                ldsm4(&bl[g * 4], uBlo + off);
            }
            #pragma unroll
            for (int i = 0; i < 2; i++)
                #pragma unroll
                for (int j = 0; j < 8; j++) {
                    mma16816(acc[i][j], ah[i], &bh[j * 2]);
                    mma16816(acc[i][j], ah[i], &bl[j * 2]);
                    mma16816(acc[i][j], al[i], &bh[j * 2]);
                }
        }
        __syncthreads();
    }

    const int mrowW = rowBase + warpM * 32;
    const int ncolW = colBase + warpN * 64;
    #pragma unroll
    for (int i = 0; i < 2; i++) {
        const int r0 = mrowW + i * 16 + (lane >> 2);
        const int r1 = r0 + 8;
        #pragma unroll
        for (int j = 0; j < 8; j++) {
            const int col = ncolW + j * 8 + (lane & 3) * 2;
            float v0 = acc[i][j][0], v1 = acc[i][j][1];
            float v2 = acc[i][j][2], v3 = acc[i][j][3];
            if (bias) {
                const float b0 = bias[col], b1 = bias[col + 1];
                v0 += b0; v1 += b1; v2 += b0; v3 += b1;
            }
            if (doGelu) {
                v0 = gelu_exact(v0); v1 = gelu_exact(v1);
                v2 = gelu_exact(v2); v3 = gelu_exact(v3);
            }
            if (Cf) {
                *(float2*)(Cf + (size_t)r0 * Nd + col) = make_float2(v0, v1);
                *(float2*)(Cf + (size_t)r1 * Nd + col) = make_float2(v2, v3);
            }
            if (Chi) {
                bf16 h0,l0,h1,l1;
                split2(v0, h0, l0); split2(v1, h1, l1);
                *(bf162*)(Chi + (size_t)r0 * Nd + col) = bf162(h0, h1);
                *(bf162*)(Clo + (size_t)r0 * Nd + col) = bf162(l0, l1);
                split2(v2, h0, l0); split2(v3, h1, l1);
                *(bf162*)(Chi + (size_t)r1 * Nd + col) = bf162(h0, h1);
                *(bf162*)(Clo + (size_t)r1 * Nd + col) = bf162(l0, l1);
            }
        }
    }
}

// ---------------- QKV stage 2: emits split bf16 Q(scaled)/K/V ----------------
__global__ __launch_bounds__(256)
void qkv2_kernel(const float* __restrict__ T,
                 const float* __restrict__ Vq, const float* __restrict__ Vk, const float* __restrict__ Vv,
                 const float* __restrict__ bq, const float* __restrict__ bk, const float* __restrict__ bv,
                 bf16* __restrict__ Qh, bf16* __restrict__ Ql,
                 bf16* __restrict__ Kh, bf16* __restrict__ Kl,
                 bf16* __restrict__ Vvh, bf16* __restrict__ Vvl) {
    __shared__ float Ts[HH*RR];
    const int bm = blockIdx.x;
    const int which = blockIdx.y;
    const float* Vw = (which == 0) ? Vq : (which == 1) ? Vk : Vv;
    const float* bw = (which == 0) ? bq : (which == 1) ? bk : bv;
    bf16* Oh = (which == 0) ? Qh : (which == 1) ? Kh : Vvh;
    bf16* Ol = (which == 0) ? Ql : (which == 1) ? Kl : Vvl;

    for (int i = threadIdx.x; i < HH*RR; i += 256)
        Ts[i] = T[(size_t)bm * NCAT + which * (HH*RR) + i];
    __syncthreads();

    const int b = bm / MM;
    const int m = bm - b * MM;
    const float sc = (which == 0) ? 0.125f : 1.0f;
    for (int o = threadIdx.x; o < HH * DHD; o += 256) {
        int h = o >> 6;
        int d = o & 63;
        float acc = bw[h * DHD + d];
        const float* w = Vw + (size_t)h * (RR * DHD) + d;
        const float* ts = Ts + h * RR;
        #pragma unroll
        for (int r = 0; r < RR; r++)
            acc += ts[r] * w[r * DHD];
        acc *= sc;
        bf16 hh, ll;
        split2(acc, hh, ll);
        const size_t idx = (((size_t)b * HH + h) * MM + m) * DHD + d;
        Oh[idx] = hh; Ol[idx] = ll;
    }
}

// ---------------- tensor-core flash attention ----------------
// CTA: 128 queries x one (b,h). 8 warps x 16 rows. KV tiles of 64 keys.
__global__ __launch_bounds__(256)
void flash_mma_kernel(const bf16* __restrict__ Qh, const bf16* __restrict__ Ql,
                      const bf16* __restrict__ Kh, const bf16* __restrict__ Kl,
                      const bf16* __restrict__ Vh, const bf16* __restrict__ Vl,
                      const float* __restrict__ mask,
                      bf16* __restrict__ out_hi, bf16* __restrict__ out_lo) {
    __shared__ bf16 smT[4][64 * 64];     // KV tiles: Khi, Klo, Vhi, Vlo (8KB each)
    __shared__ float sMk[64];

    const int t    = threadIdx.x;
    const int wid  = t >> 5;
    const int lane = t & 31;
    const int bh   = blockIdx.y;
    const int b    = bh / HH;
    const int h    = bh - b * HH;
    const int qBase = blockIdx.x * 128;

    const uint32_t uT0 = smem_u32(&smT[0][0]);
    const uint32_t uT1 = smem_u32(&smT[1][0]);
    const uint32_t uT2 = smem_u32(&smT[2][0]);
    const uint32_t uT3 = smem_u32(&smT[3][0]);

    // ---- stage Q (128x64 hi/lo) into smem, then ldmatrix into registers ----
    {
        bf16* smQh = &smT[0][0];           // 16KB spans smT[0..1]
        bf16* smQl = &smT[2][0];           // 16KB spans smT[2..3]
        const bf16* gQh = Qh + ((size_t)bh * MM + qBase) * DHD;
        const bf16* gQl = Ql + ((size_t)bh * MM + qBase) * DHD;
        #pragma unroll
        for (int i = 0; i < 4; i++) {
            const int idx = t + i * 256;       // 0..1023
            const int row = idx >> 3;
            const int seg = idx & 7;
            const uint32_t off = (uint32_t)(row * 64 + ((seg ^ (row & 7)) << 3));
            *(uint4*)(smQh + off) = *(const uint4*)(gQh + row * 64 + seg * 8);
            *(uint4*)(smQl + off) = *(const uint4*)(gQl + row * 64 + seg * 8);
        }
    }
    __syncthreads();

    uint32_t qfh[4][4], qfl[4][4];
    {
        const int ar = wid * 16 + (lane & 15);
        const int alsel = lane >> 4;
        #pragma unroll
        for (int kk = 0; kk < 4; kk++) {
            const int cc = kk * 2 + alsel;
            const uint32_t off = (uint32_t)(ar * 128 + ((cc ^ (ar & 7)) << 4));
            ldsm4(qfh[kk], uT0 + off);
            ldsm4(qfl[kk], uT2 + off);
        }
    }
    __syncthreads();

    // ---- state ----
    float O[8][4];
    #pragma unroll
    for (int j = 0; j < 8; j++)
        #pragma unroll
        for (int e = 0; e < 4; e++) O[j][e] = 0.0f;
    float m0 = -1e30f, m1 = -1e30f, l0 = 0.0f, l1 = 0.0f;

    const int brow0 = (lane & 7) + ((lane >> 4) << 3);
    const int bcsel = (lane >> 3) & 1;
    const int kvrow = t >> 2;
    const int kvs0  = (t & 3) * 2;

    for (int nb = 0; nb < MM / 64; nb++) {
        const int n0 = nb * 64;
        // ---- load KV tiles (hi/lo) + mask ----
        {
            const bf16* gKh = Kh + ((size_t)bh * MM + n0 + kvrow) * DHD;
            const bf16* gKl = Kl + ((size_t)bh * MM + n0 + kvrow) * DHD;
            const bf16* gVh = Vh + ((size_t)bh * MM + n0 + kvrow) * DHD;
            const bf16* gVl = Vl + ((size_t)bh * MM + n0 + kvrow) * DHD;
            #pragma unroll
            for (int si = 0; si < 2; si++) {
                const int seg = kvs0 + si;
                const uint32_t off = (uint32_t)(kvrow * 64 + ((seg ^ (kvrow & 7)) << 3));
                *(uint4*)(&smT[0][0] + off) = *(const uint4*)(gKh + seg * 8);
                *(uint4*)(&smT[1][0] + off) = *(const uint4*)(gKl + seg * 8);
                *(uint4*)(&smT[2][0] + off) = *(const uint4*)(gVh + seg * 8);
                *(uint4*)(&smT[3][0] + off) = *(const uint4*)(gVl + seg * 8);
            }
            if (t < 64) sMk[t] = mask[(size_t)b * MM + n0 + t];
        }
        __syncthreads();

        // ---- S = Q @ K^T (3-pass split, fp32 accum) ----
        float s[8][4];
        #pragma unroll
        for (int j = 0; j < 8; j++)
            #pragma unroll
            for (int e = 0; e < 4; e++) s[j][e] = 0.0f;

        #pragma unroll
        for (int kk = 0; kk < 4; kk++) {
            uint32_t kb[16], kbl[16];
            #pragma unroll
            for (int g = 0; g < 4; g++) {
                const int br = brow0 + g * 16;
                const int cc = kk * 2 + bcsel;
                const uint32_t off = (uint32_t)(br * 128 + ((cc ^ (br & 7)) << 4));
                ldsm4(&kb[g * 4],  uT0 + off);
                ldsm4(&kbl[g * 4], uT1 + off);
            }
            #pragma unroll
            for (int j = 0; j < 8; j++) {
                mma16816(s[j], qfh[kk], &kb[j * 2]);
                mma16816(s[j], qfh[kk], &kbl[j * 2]);
                mma16816(s[j], qfl[kk], &kb[j * 2]);
            }
        }

        // ---- mask + online softmax ----
        const int c2 = (lane & 3) * 2;
        #pragma unroll
        for (int j = 0; j < 8; j++) {
            const float mka = sMk[j * 8 + c2];
            const float mkb = sMk[j * 8 + c2 + 1];
            s[j][0] += mka; s[j][1] += mkb; s[j][2] += mka; s[j][3] += mkb;
        }
        float mx0 = -1e30f, mx1 = -1e30f;
        #pragma unroll
        for (int j = 0; j < 8; j++) {
            mx0 = fmaxf(mx0, fmaxf(s[j][0], s[j][1]));
            mx1 = fmaxf(mx1, fmaxf(s[j][2], s[j][3]));
        }
        mx0 = fmaxf(mx0, __shfl_xor_sync(0xffffffffu, mx0, 1));
        mx0 = fmaxf(mx0, __shfl_xor_sync(0xffffffffu, mx0, 2));
        mx1 = fmaxf(mx1, __shfl_xor_sync(0xffffffffu, mx1, 1));
        mx1 = fmaxf(mx1, __shfl_xor_sync(0xffffffffu, mx1, 2));
        const float mn0 = fmaxf(m0, mx0);
        const float mn1 = fmaxf(m1, mx1);
        const float cr0 = __expf(m0 - mn0);
        const float cr1 = __expf(m1 - mn1);
        m0 = mn0; m1 = mn1;
        l0 *= cr0; l1 *= cr1;
        #pragma unroll
        for (int j = 0; j < 8; j++) {
            O[j][0] *= cr0; O[j][1] *= cr0;
            O[j][2] *= cr1; O[j][3] *= cr1;
        }

        // ---- P = exp(S - m), split+pack into A fragments ----
        uint32_t pahi[4][4], palo[4][4];
        #pragma unroll
        for (int j = 0; j < 8; j++) {
            const float p0 = __expf(s[j][0] - m0);
            const float p1 = __expf(s[j][1] - m0);
            const float p2 = __expf(s[j][2] - m1);
            const float p3 = __expf(s[j][3] - m1);
            l0 += p0 + p1;
            l1 += p2 + p3;
            const int kk = j >> 1, hf = (j & 1) * 2;
            split_pack(p0, p1, pahi[kk][hf],     palo[kk][hf]);
            split_pack(p2, p3, pahi[kk][hf + 1], palo[kk][hf + 1]);
        }

        // ---- O += P @ V (3-pass split) ----
        #pragma unroll
        for (int kk = 0; kk < 4; kk++) {
            uint32_t vh4[4][4], vl4[4][4];
            const int krow = kk * 16 + ((lane >> 3) & 1) * 8 + (lane & 7);
            #pragma unroll
            for (int g = 0; g < 4; g++) {
                const int cc = g * 2 + (lane >> 4);
                const uint32_t off = (uint32_t)(krow * 128 + ((cc ^ (krow & 7)) << 4));
                ldsm4t(vh4[g], uT2 + off);
                ldsm4t(vl4[g], uT3 + off);
            }
            #pragma unroll
            for (int jn = 0; jn < 8; jn++) {
                const int g = jn >> 1, sub = (jn & 1) * 2;
                mma16816(O[jn], pahi[kk], &vh4[g][sub]);
                mma16816(O[jn], palo[kk], &vh4[g][sub]);
                mma16816(O[jn], pahi[kk], &vl4[g][sub]);
            }
        }
        __syncthreads();
    }

    // ---- epilogue ----
    l0 += __shfl_xor_sync(0xffffffffu, l0, 1);
    l0 += __shfl_xor_sync(0xffffffffu, l0, 2);
    l1 += __shfl_xor_sync(0xffffffffu, l1, 1);
    l1 += __shfl_xor_sync(0xffffffffu, l1, 2);
    const float inv0 = 1.0f / l0;
    const float inv1 = 1.0f / l1;

    const int mrow0 = qBase + wid * 16 + (lane >> 2);
    const int mrow1 = mrow0 + 8;
    #pragma unroll
    for (int jn = 0; jn < 8; jn++) {
        const int col = h * DHD + jn * 8 + (lane & 3) * 2;
        uint32_t h01, l01, h23, l23;
        split_pack(O[jn][0] * inv0, O[jn][1] * inv0, h01, l01);
        split_pack(O[jn][2] * inv1, O[jn][3] * inv1, h23, l23);
        const size_t i0 = ((size_t)b * MM + mrow0) * DM + col;
        const size_t i1 = ((size_t)b * MM + mrow1) * DM + col;
        *(uint32_t*)(out_hi + i0) = h01;
        *(uint32_t*)(out_lo + i0) = l01;
        *(uint32_t*)(out_hi + i1) = h23;
        *(uint32_t*)(out_lo + i1) = l23;
    }
}

// ---------------- LayerNorm(xa + xb) * g + b, over 768; optional split output ----------------
__global__ __launch_bounds__(256)
void ln_kernel(const float* __restrict__ xa, const float* __restrict__ xb,
               const float* __restrict__ gw, const float* __restrict__ bw,
               float* __restrict__ out, bf16* __restrict__ ohi, bf16* __restrict__ olo) {
    const int row = blockIdx.x;
    const int t = threadIdx.x;
    const float* pa = xa + (size_t)row * DM;
    const float* pb = xb + (size_t)row * DM;

    float v0 = pa[t]       + pb[t];
    float v1 = pa[t + 256] + pb[t + 256];
    float v2 = pa[t + 512] + pb[t + 512];

    float s  = v0 + v1 + v2;
    float ss = v0 * v0 + v1 * v1 + v2 * v2;
    #pragma unroll
    for (int off = 16; off > 0; off >>= 1) {
        s  += __shfl_xor_sync(0xffffffffu, s,  off);
        ss += __shfl_xor_sync(0xffffffffu, ss, off);
    }
    __shared__ float wsum[8], wsq[8], stats[2];
    int warp = t >> 5;
    if ((t & 31) == 0) { wsum[warp] = s; wsq[warp] = ss; }
    __syncthreads();
    if (t == 0) {
        float S = 0.f, SS = 0.f;
        #pragma unroll
        for (int w = 0; w < 8; w++) { S += wsum[w]; SS += wsq[w]; }
        float mu = S * (1.0f / DM);
        float var = SS * (1.0f / DM) - mu * mu;
        stats[0] = mu;
        stats[1] = rsqrtf(var + 1e-12f);
    }
    __syncthreads();
    float mu = stats[0], rstd = stats[1];
    float* po = out + (size_t)row * DM;
    float r0 = (v0 - mu) * rstd * gw[t]       + bw[t];
    float r1 = (v1 - mu) * rstd * gw[t + 256] + bw[t + 256];
    float r2 = (v2 - mu) * rstd * gw[t + 512] + bw[t + 512];
    po[t] = r0; po[t + 256] = r1; po[t + 512] = r2;
    if (ohi) {
        bf16 hh, ll;
        split2(r0, hh, ll); ohi[(size_t)row*DM + t]       = hh; olo[(size_t)row*DM + t]       = ll;
        split2(r1, hh, ll); ohi[(size_t)row*DM + t + 256] = hh; olo[(size_t)row*DM + t + 256] = ll;
        split2(r2, hh, ll); ohi[(size_t)row*DM + t + 512] = hh; olo[(size_t)row*DM + t + 512] = ll;
    }
}

// ---------------- launch ----------------
static inline void launch_mma(const bf16* Ahi, const bf16* Alo, const bf16* Bhi, const bf16* Blo,
                              const float* bias, float* Cf, bf16* Chi, bf16* Clo,
                              int Md, int Nd, int Kd, int doGelu) {
    dim3 grid(Nd / 128, Md / 128);
    mma_gemm_kernel<<<grid, 256, SMEM_GEMM>>>(Ahi, Alo, Bhi, Blo, bias, Cf, Chi, Clo,
                                              Md, Nd, Kd, doGelu);
}

extern "C" void kernel_launch(void* const* d_in, const int* in_sizes, int n_in,
                              void* d_out, int out_size) {
    const float* x    = (const float*)d_in[0];
    const float* mask = (const float*)d_in[1];
    const float* Pq   = (const float*)d_in[2];
    const float* Vq   = (const float*)d_in[3];
    const float* bq   = (const float*)d_in[4];
    const float* Pk   = (const float*)d_in[5];
    const float* Vk   = (const float*)d_in[6];
    const float* bk   = (const float*)d_in[7];
    const float* Pv   = (const float*)d_in[8];
    const float* Vv   = (const float*)d_in[9];
    const float* bv   = (const float*)d_in[10];
    const float* Uo   = (const float*)d_in[11];
    const float* Vo   = (const float*)d_in[12];
    const float* bo   = (const float*)d_in[13];
    const float* U1   = (const float*)d_in[14];
    const float* V1   = (const float*)d_in[15];
    const float* b1   = (const float*)d_in[16];
    const float* U2   = (const float*)d_in[17];
    const float* V2   = (const float*)d_in[18];
    const float* b2   = (const float*)d_in[19];
    const float* ln1g = (const float*)d_in[20];
    const float* ln1b = (const float*)d_in[21];
    const float* ln2g = (const float*)d_in[22];
    const float* ln2b = (const float*)d_in[23];

    static bool attrSet = false;
    if (!attrSet) {
        cudaFuncSetAttribute(mma_gemm_kernel, cudaFuncAttributeMaxDynamicSharedMemorySize, SMEM_GEMM);
        attrSet = true;
    }

    float *pT, *pQ, *pK, *pV, *pTmp, *pX1;
    cudaGetSymbolAddress((void**)&pT,   g_T);
    cudaGetSymbolAddress((void**)&pQ,   g_Q);
    cudaGetSymbolAddress((void**)&pK,   g_K);
    cudaGetSymbolAddress((void**)&pV,   g_V);
    cudaGetSymbolAddress((void**)&pTmp, g_tmp);
    cudaGetSymbolAddress((void**)&pX1,  g_x1);

    // alias split Q/K/V into the fp32 buffers (hi | lo halves)
    bf16* qh = (bf16*)pQ;  bf16* ql = qh + (size_t)BMTOT * DM;
    bf16* kh = (bf16*)pK;  bf16* kl = kh + (size_t)BMTOT * DM;
    bf16* vh = (bf16*)pV;  bf16* vl = vh + (size_t)BMTOT * DM;

    bf16 *xsH,*xsL,*asH,*asL,*msH,*msL,*x1H,*x1L,*hsH,*hsL;
    bf16 *ptH,*ptL,*uoH,*uoL,*voH,*voL,*u1H,*u1L,*v1H,*v1L,*u2H,*u2L,*v2H,*v2L;
    cudaGetSymbolAddress((void**)&xsH, g_xs_hi);  cudaGetSymbolAddress((void**)&xsL, g_xs_lo);
    cudaGetSymbolAddress((void**)&asH, g_as_hi);  cudaGetSymbolAddress((void**)&asL, g_as_lo);
    cudaGetSymbolAddress((void**)&msH, g_ms_hi);  cudaGetSymbolAddress((void**)&msL, g_ms_lo);
    cudaGetSymbolAddress((void**)&x1H, g_x1s_hi); cudaGetSymbolAddress((void**)&x1L, g_x1s_lo);
    cudaGetSymbolAddress((void**)&hsH, g_hs_hi);  cudaGetSymbolAddress((void**)&hsL, g_hs_lo);
    cudaGetSymbolAddress((void**)&ptH, g_ptT_hi); cudaGetSymbolAddress((void**)&ptL, g_ptT_lo);
    cudaGetSymbolAddress((void**)&uoH, g_uoT_hi); cudaGetSymbolAddress((void**)&uoL, g_uoT_lo);
    cudaGetSymbolAddress((void**)&voH, g_voT_hi); cudaGetSymbolAddress((void**)&voL, g_voT_lo);
    cudaGetSymbolAddress((void**)&u1H, g_u1T_hi); cudaGetSymbolAddress((void**)&u1L, g_u1T_lo);
    cudaGetSymbolAddress((void**)&v1H, g_v1T_hi); cudaGetSymbolAddress((void**)&v1L, g_v1T_lo);
    cudaGetSymbolAddress((void**)&u2H, g_u2T_hi); cudaGetSymbolAddress((void**)&u2L, g_u2T_lo);
    cudaGetSymbolAddress((void**)&v2H, g_v2T_hi); cudaGetSymbolAddress((void**)&v2L, g_v2T_lo);

    // ---- weight conversions ----
    permutePtT_kernel<<<(NCAT * DM + 255) / 256, 256>>>(Pq, Pk, Pv, ptH, ptL);
    splitWT_kernel<<<(DM * RFF + 255) / 256, 256>>>(Uo, uoH, uoL, DM, RFF);
    splitWT_kernel<<<(RFF * DM + 255) / 256, 256>>>(Vo, voH, voL, RFF, DM);
    splitWT_kernel<<<(DM * RFF + 255) / 256, 256>>>(U1, u1H, u1L, DM, RFF);
    splitWT_kernel<<<(RFF * DFF + 255) / 256, 256>>>(V1, v1H, v1L, RFF, DFF);
    splitWT_kernel<<<(DFF * RFF + 255) / 256, 256>>>(U2, u2H, u2L, DFF, RFF);
    splitWT_kernel<<<(RFF * DM + 255) / 256, 256>>>(V2, v2H, v2L, RFF, DM);

    // ---- 1) split x; T = x @ Pt ----
    split_act_kernel<<<(BMTOT * DM / 4 + 255) / 256, 256>>>(x, xsH, xsL, BMTOT * DM / 4);
    launch_mma(xsH, xsL, ptH, ptL, nullptr, pT, nullptr, nullptr, BMTOT, NCAT, DM, 0);

    // ---- 2) QKV stage 2 (split bf16 out, Q pre-scaled) ----
    qkv2_kernel<<<dim3(BMTOT, 3), 256>>>(pT, Vq, Vk, Vv, bq, bk, bv, qh, ql, kh, kl, vh, vl);

    // ---- 3) tensor-core flash attention -> attn split ----
    flash_mma_kernel<<<dim3(MM / 128, BB * HH), 256>>>(qh, ql, kh, kl, vh, vl, mask, asH, asL);

    // ---- 4) Wo low-rank + LN1 ----
    launch_mma(asH, asL, uoH, uoL, nullptr, nullptr, msH, msL, BMTOT, RFF, DM, 0);
    launch_mma(msH, msL, voH, voL, bo, pTmp, nullptr, nullptr, BMTOT, DM, RFF, 0);
    ln_kernel<<<BMTOT, 256>>>(x, pTmp, ln1g, ln1b, pX1, x1H, x1L);

    // ---- 5) FFN ----
    launch_mma(x1H, x1L, u1H, u1L, nullptr, nullptr, msH, msL, BMTOT, RFF, DM, 0);
    launch_mma(msH, msL, v1H, v1L, b1, nullptr, hsH, hsL, BMTOT, DFF, RFF, 1);
    launch_mma(hsH, hsL, u2H, u2L, nullptr, nullptr, msH, msL, BMTOT, RFF, DFF, 0);
    launch_mma(msH, msL, v2H, v2L, b2, pTmp, nullptr, nullptr, BMTOT, DM, RFF, 0);
    ln_kernel<<<BMTOT, 256>>>(pX1, pTmp, ln2g, ln2b, (float*)d_out, nullptr, nullptr);
}

// round 13
// speedup vs baseline: 3.5900x; 1.2408x over previous
#include <cuda_runtime.h>
#include <cuda_bf16.h>
#include <math.h>
#include <stdint.h>

// ---------------- problem constants ----------------
#define BB    8
#define MM    1024
#define DM    768
#define HH    12
#define DHD   64
#define RR    32
#define RFF   384
#define DFF   3072
#define BMTOT (BB*MM)          // 8192
#define NCAT  (3*HH*RR)        // 1152

typedef __nv_bfloat16 bf16;
typedef __nv_bfloat162 bf162;

// ---------------- scratch (device globals; no allocs allowed) ----------------
__device__ float g_T   [BMTOT* NCAT];
__device__ float g_Q   [BMTOT* DM];       // reused as split bf16 Qhi|Qlo
__device__ float g_K   [BMTOT* DM];       // reused as split bf16 Khi|Klo
__device__ float g_V   [BMTOT* DM];       // reused as split bf16 Vhi|Vlo
__device__ float g_tmp [BMTOT* DM];
__device__ float g_x1  [BMTOT* DM];
__device__ bf16 g_xs_hi [BMTOT*DM],  g_xs_lo [BMTOT*DM];
__device__ bf16 g_as_hi [BMTOT*DM],  g_as_lo [BMTOT*DM];
__device__ bf16 g_ms_hi [BMTOT*RFF], g_ms_lo [BMTOT*RFF];
__device__ bf16 g_x1s_hi[BMTOT*DM],  g_x1s_lo[BMTOT*DM];
__device__ bf16 g_hs_hi [BMTOT*DFF], g_hs_lo [BMTOT*DFF];
__device__ bf16 g_ptT_hi[NCAT*DM],  g_ptT_lo[NCAT*DM];
__device__ bf16 g_uoT_hi[RFF*DM],   g_uoT_lo[RFF*DM];
__device__ bf16 g_voT_hi[DM*RFF],   g_voT_lo[DM*RFF];
__device__ bf16 g_u1T_hi[RFF*DM],   g_u1T_lo[RFF*DM];
__device__ bf16 g_v1T_hi[DFF*RFF],  g_v1T_lo[DFF*RFF];
__device__ bf16 g_u2T_hi[RFF*DFF],  g_u2T_lo[RFF*DFF];
__device__ bf16 g_v2T_hi[DM*RFF],   g_v2T_lo[DM*RFF];

// ---------------- helpers ----------------
__device__ __forceinline__ float gelu_exact(float v) {
    return 0.5f * v * (1.0f + erff(v * 0.70710678118654752440f));
}

__device__ __forceinline__ void split2(float v, bf16& h, bf16& l) {
    h = __float2bfloat16(v);
    l = __float2bfloat16(v - __bfloat162float(h));
}

__device__ __forceinline__ void split_pack(float a, float b, uint32_t& hi, uint32_t& lo) {
    bf16 ha, la, hb, lb;
    split2(a, ha, la); split2(b, hb, lb);
    bf162 th(ha, hb), tl(la, lb);
    hi = *(uint32_t*)&th; lo = *(uint32_t*)&tl;
}

__device__ __forceinline__ uint32_t smem_u32(const void* p) {
    uint32_t a;
    asm("{ .reg .u64 t; cvta.to.shared.u64 t, %1; cvt.u32.u64 %0, t; }" : "=r"(a) : "l"(p));
    return a;
}

__device__ __forceinline__ void ldsm4(uint32_t* r, uint32_t addr) {
    asm volatile("ldmatrix.sync.aligned.m8n8.x4.shared.b16 {%0,%1,%2,%3}, [%4];"
                 : "=r"(r[0]), "=r"(r[1]), "=r"(r[2]), "=r"(r[3]) : "r"(addr));
}
__device__ __forceinline__ void ldsm4t(uint32_t* r, uint32_t addr) {
    asm volatile("ldmatrix.sync.aligned.m8n8.x4.trans.shared.b16 {%0,%1,%2,%3}, [%4];"
                 : "=r"(r[0]), "=r"(r[1]), "=r"(r[2]), "=r"(r[3]) : "r"(addr));
}

__device__ __forceinline__ void mma16816(float* d, const uint32_t* a, const uint32_t* b) {
    asm volatile(
        "mma.sync.aligned.m16n8k16.row.col.f32.bf16.bf16.f32 "
        "{%0,%1,%2,%3}, {%4,%5,%6,%7}, {%8,%9}, {%0,%1,%2,%3};"
        : "+f"(d[0]), "+f"(d[1]), "+f"(d[2]), "+f"(d[3])
        : "r"(a[0]), "r"(a[1]), "r"(a[2]), "r"(a[3]), "r"(b[0]), "r"(b[1]));
}

__device__ __forceinline__ void cp16(uint32_t dst, const void* src) {
    asm volatile("cp.async.cg.shared.global [%0], [%1], 16;" :: "r"(dst), "l"(src));
}
__device__ __forceinline__ void cp_commit() {
    asm volatile("cp.async.commit_group;" ::: "memory");
}
template<int N>
__device__ __forceinline__ void cp_wait() {
    asm volatile("cp.async.wait_group %0;" :: "n"(N) : "memory");
}

// ---------------- conversion kernels ----------------
__global__ void split_act_kernel(const float* __restrict__ A, bf16* __restrict__ hi,
                                 bf16* __restrict__ lo, int n4) {
    int i = blockIdx.x * 256 + threadIdx.x;
    if (i >= n4) return;
    float4 v = ((const float4*)A)[i];
    bf16 h0, l0, h1, l1, h2, l2, h3, l3;
    split2(v.x, h0, l0); split2(v.y, h1, l1); split2(v.z, h2, l2); split2(v.w, h3, l3);
    bf162* ph = (bf162*)(hi + (size_t)i * 4);
    bf162* pl = (bf162*)(lo + (size_t)i * 4);
    ph[0] = bf162(h0, h1); ph[1] = bf162(h2, h3);
    pl[0] = bf162(l0, l1); pl[1] = bf162(l2, l3);
}

__global__ void splitWT_kernel(const float* __restrict__ W, bf16* __restrict__ hiT,
                               bf16* __restrict__ loT, int K, int N) {
    int i = blockIdx.x * 256 + threadIdx.x;
    if (i >= K * N) return;
    int n = i / K;
    int k = i - n * K;
    bf16 h, l;
    split2(W[(size_t)k * N + n], h, l);
    hiT[i] = h; loT[i] = l;
}

__global__ void permutePtT_kernel(const float* __restrict__ Pq, const float* __restrict__ Pk,
                                  const float* __restrict__ Pv,
                                  bf16* __restrict__ hiT, bf16* __restrict__ loT) {
    int idx = blockIdx.x * 256 + threadIdx.x;
    if (idx >= NCAT * DM) return;
    int n = idx / DM;
    int d = idx - n * DM;
    int which = n / (HH*RR);
    int hn = n - which * (HH*RR);
    int h = hn >> 5;
    int r = hn & 31;
    const float* P = (which == 0) ? Pq : (which == 1) ? Pk : Pv;
    bf16 hh, ll;
    split2(P[((size_t)h * DM + d) * RR + r], hh, ll);
    hiT[idx] = hh; loT[idx] = ll;
}

// ---------------- cp.async double-buffered split-bf16 GEMM ----------------
// C[M,N] = A[M,K] @ B^T, B stored [N,K] K-major. CTA tile 128x128, K chunk 32, 2 stages.
#define KC 32
#define TILE_B (128 * KC * 2)          // 8192 bytes per tile
#define STAGE_B (4 * TILE_B)           // 32768 bytes per stage
#define SMEM_GEMM (2 * STAGE_B)        // 65536 bytes

// swizzled byte offset within a 128xKC tile: row stride 64B, seg = 16B unit (0..3)
__device__ __forceinline__ uint32_t sw32(int row, int seg) {
    return (uint32_t)(row * 64 + ((seg ^ ((row >> 1) & 3)) << 4));
}

__global__ __launch_bounds__(256)
void mma_gemm_kernel(const bf16* __restrict__ Ahi, const bf16* __restrict__ Alo,
                     const bf16* __restrict__ Bhi, const bf16* __restrict__ Blo,
                     const float* __restrict__ bias,
                     float* __restrict__ Cf, bf16* __restrict__ Chi, bf16* __restrict__ Clo,
                     int Md, int Nd, int Kd, int doGelu) {
    extern __shared__ char smraw[];
    const uint32_t smem_base = smem_u32(smraw);

    const int tid  = threadIdx.x;
    const int wid  = tid >> 5;
    const int lane = tid & 31;
    const int warpM = wid & 3;
    const int warpN = wid >> 2;
    const int rowBase = blockIdx.y * 128;
    const int colBase = blockIdx.x * 128;

    // prefetch mapping: thread -> row = tid>>1, 2 x 16B segs per tile
    const int lrow  = tid >> 1;
    const int lseg0 = (tid & 1) * 2;
    const bf16* gA = Ahi + (size_t)(rowBase + lrow) * Kd;
    const bf16* gAl = Alo + (size_t)(rowBase + lrow) * Kd;
    const bf16* gB = Bhi + (size_t)(colBase + lrow) * Kd;
    const bf16* gBl = Blo + (size_t)(colBase + lrow) * Kd;

    float acc[2][8][4];
    #pragma unroll
    for (int i = 0; i < 2; i++)
        #pragma unroll
        for (int j = 0; j < 8; j++)
            #pragma unroll
            for (int e = 0; e < 4; e++) acc[i][j][e] = 0.0f;

    const int arow0 = warpM * 32 + (lane & 15);
    const int alsel = lane >> 4;
    const int brow0 = warpN * 64 + (lane & 7) + ((lane >> 4) << 3);
    const int bcsel = (lane >> 3) & 1;

    const int nChunks = Kd / KC;

    // ---- prefetch chunk 0 ----
    {
        const uint32_t sb = smem_base;
        #pragma unroll
        for (int si = 0; si < 2; si++) {
            const int seg = lseg0 + si;
            const uint32_t off = sw32(lrow, seg);
            cp16(sb + off,              gA  + seg * 8);
            cp16(sb + TILE_B + off,     gAl + seg * 8);
            cp16(sb + 2*TILE_B + off,   gB  + seg * 8);
            cp16(sb + 3*TILE_B + off,   gBl + seg * 8);
        }
        cp_commit();
    }

    for (int c = 0; c < nChunks; c++) {
        const int cur = c & 1;
        if (c + 1 < nChunks) {
            const int k0 = (c + 1) * KC;
            const uint32_t sb = smem_base + (cur ^ 1) * STAGE_B;
            #pragma unroll
            for (int si = 0; si < 2; si++) {
                const int seg = lseg0 + si;
                const uint32_t off = sw32(lrow, seg);
                cp16(sb + off,              gA  + k0 + seg * 8);
                cp16(sb + TILE_B + off,     gAl + k0 + seg * 8);
                cp16(sb + 2*TILE_B + off,   gB  + k0 + seg * 8);
                cp16(sb + 3*TILE_B + off,   gBl + k0 + seg * 8);
            }
            cp_commit();
            cp_wait<1>();
        } else {
            cp_wait<0>();
        }
        __syncthreads();

        const uint32_t sb = smem_base + cur * STAGE_B;
        #pragma unroll
        for (int kk = 0; kk < 2; kk++) {
            uint32_t ah[2][4], al[2][4], bh[16], bl[16];
            #pragma unroll
            for (int i = 0; i < 2; i++) {
                const int ar = arow0 + i * 16;
                const uint32_t off = sw32(ar, kk * 2 + alsel);
                ldsm4(ah[i], sb + off);
                ldsm4(al[i], sb + TILE_B + off);
            }
            #pragma unroll
            for (int g = 0; g < 4; g++) {
                const int br = brow0 + g * 16;
                const uint32_t off = sw32(br, kk * 2 + bcsel);
                ldsm4(&bh[g * 4], sb + 2*TILE_B + off);
                ldsm4(&bl[g * 4], sb + 3*TILE_B + off);
            }
            #pragma unroll
            for (int i = 0; i < 2; i++)
                #pragma unroll
                for (int j = 0; j < 8; j++) {
                    mma16816(acc[i][j], ah[i], &bh[j * 2]);
                    mma16816(acc[i][j], ah[i], &bl[j * 2]);
                    mma16816(acc[i][j], al[i], &bh[j * 2]);
                }
        }
        __syncthreads();
    }

    const int mrowW = rowBase + warpM * 32;
    const int ncolW = colBase + warpN * 64;
    #pragma unroll
    for (int i = 0; i < 2; i++) {
        const int r0 = mrowW + i * 16 + (lane >> 2);
        const int r1 = r0 + 8;
        #pragma unroll
        for (int j = 0; j < 8; j++) {
            const int col = ncolW + j * 8 + (lane & 3) * 2;
            float v0 = acc[i][j][0], v1 = acc[i][j][1];
            float v2 = acc[i][j][2], v3 = acc[i][j][3];
            if (bias) {
                const float b0 = bias[col], b1 = bias[col + 1];
                v0 += b0; v1 += b1; v2 += b0; v3 += b1;
            }
            if (doGelu) {
                v0 = gelu_exact(v0); v1 = gelu_exact(v1);
                v2 = gelu_exact(v2); v3 = gelu_exact(v3);
            }
            if (Cf) {
                *(float2*)(Cf + (size_t)r0 * Nd + col) = make_float2(v0, v1);
                *(float2*)(Cf + (size_t)r1 * Nd + col) = make_float2(v2, v3);
            }
            if (Chi) {
                uint32_t hh, ll;
                split_pack(v0, v1, hh, ll);
                *(uint32_t*)(Chi + (size_t)r0 * Nd + col) = hh;
                *(uint32_t*)(Clo + (size_t)r0 * Nd + col) = ll;
                split_pack(v2, v3, hh, ll);
                *(uint32_t*)(Chi + (size_t)r1 * Nd + col) = hh;
                *(uint32_t*)(Clo + (size_t)r1 * Nd + col) = ll;
            }
        }
    }
}

// ---------------- QKV stage 2: emits split bf16 Q(scaled)/K/V ----------------
__global__ __launch_bounds__(256)
void qkv2_kernel(const float* __restrict__ T,
                 const float* __restrict__ Vq, const float* __restrict__ Vk, const float* __restrict__ Vv,
                 const float* __restrict__ bq, const float* __restrict__ bk, const float* __restrict__ bv,
                 bf16* __restrict__ Qh, bf16* __restrict__ Ql,
                 bf16* __restrict__ Kh, bf16* __restrict__ Kl,
                 bf16* __restrict__ Vvh, bf16* __restrict__ Vvl) {
    __shared__ float Ts[HH*RR];
    const int bm = blockIdx.x;
    const int which = blockIdx.y;
    const float* Vw = (which == 0) ? Vq : (which == 1) ? Vk : Vv;
    const float* bw = (which == 0) ? bq : (which == 1) ? bk : bv;
    bf16* Oh = (which == 0) ? Qh : (which == 1) ? Kh : Vvh;
    bf16* Ol = (which == 0) ? Ql : (which == 1) ? Kl : Vvl;

    for (int i = threadIdx.x; i < HH*RR; i += 256)
        Ts[i] = T[(size_t)bm * NCAT + which * (HH*RR) + i];
    __syncthreads();

    const int b = bm / MM;
    const int m = bm - b * MM;
    const float sc = (which == 0) ? 0.125f : 1.0f;
    for (int o = threadIdx.x; o < HH * DHD; o += 256) {
        int h = o >> 6;
        int d = o & 63;
        float acc = bw[h * DHD + d];
        const float* w = Vw + (size_t)h * (RR * DHD) + d;
        const float* ts = Ts + h * RR;
        #pragma unroll
        for (int r = 0; r < RR; r++)
            acc += ts[r] * w[r * DHD];
        acc *= sc;
        bf16 hh, ll;
        split2(acc, hh, ll);
        const size_t idx = (((size_t)b * HH + h) * MM + m) * DHD + d;
        Oh[idx] = hh; Ol[idx] = ll;
    }
}

// ---------------- tensor-core flash attention, cp.async double-buffered KV ----------------
#define FT_B (64 * 64 * 2)          // 8192 bytes per KV tile
#define FSTAGE_B (4 * FT_B)         // 32768 per stage
#define SMEM_FLASH (2 * FSTAGE_B)   // 65536

__global__ __launch_bounds__(256)
void flash_mma_kernel(const bf16* __restrict__ Qh, const bf16* __restrict__ Ql,
                      const bf16* __restrict__ Kh, const bf16* __restrict__ Kl,
                      const bf16* __restrict__ Vh, const bf16* __restrict__ Vl,
                      const float* __restrict__ mask,
                      bf16* __restrict__ out_hi, bf16* __restrict__ out_lo) {
    extern __shared__ char smraw[];
    const uint32_t smem_base = smem_u32(smraw);
    __shared__ float sMk[2][64];

    const int t    = threadIdx.x;
    const int wid  = t >> 5;
    const int lane = t & 31;
    const int bh   = blockIdx.y;
    const int b    = bh / HH;
    const int h    = bh - b * HH;
    const int qBase = blockIdx.x * 128;

    // ---- stage Q (128x64 hi/lo) into stage-0 smem, load frags ----
    {
        bf16* smQh = (bf16*)smraw;              // 16KB
        bf16* smQl = (bf16*)(smraw + 2 * FT_B); // 16KB
        const bf16* gQh = Qh + ((size_t)bh * MM + qBase) * DHD;
        const bf16* gQl = Ql + ((size_t)bh * MM + qBase) * DHD;
        #pragma unroll
        for (int i = 0; i < 4; i++) {
            const int idx = t + i * 256;
            const int row = idx >> 3;
            const int seg = idx & 7;
            const uint32_t off = (uint32_t)(row * 64 + ((seg ^ (row & 7)) << 3));
            *(uint4*)(smQh + off) = *(const uint4*)(gQh + row * 64 + seg * 8);
            *(uint4*)(smQl + off) = *(const uint4*)(gQl + row * 64 + seg * 8);
        }
    }
    __syncthreads();

    uint32_t qfh[4][4], qfl[4][4];
    {
        const int ar = wid * 16 + (lane & 15);
        const int alsel = lane >> 4;
        #pragma unroll
        for (int kk = 0; kk < 4; kk++) {
            const int cc = kk * 2 + alsel;
            const uint32_t off = (uint32_t)(ar * 128 + ((cc ^ (ar & 7)) << 4));
            ldsm4(qfh[kk], smem_base + off);
            ldsm4(qfl[kk], smem_base + 2 * FT_B + off);
        }
    }
    __syncthreads();

    // ---- state ----
    float O[8][4];
    #pragma unroll
    for (int j = 0; j < 8; j++)
        #pragma unroll
        for (int e = 0; e < 4; e++) O[j][e] = 0.0f;
    float m0 = -1e30f, m1 = -1e30f, l0 = 0.0f, l1 = 0.0f;

    const int brow0 = (lane & 7) + ((lane >> 4) << 3);
    const int bcsel = (lane >> 3) & 1;
    const int kvrow = t >> 2;
    const int kvs0  = (t & 3) * 2;

    const bf16* gKh = Kh + ((size_t)bh * MM + kvrow) * DHD;
    const bf16* gKl = Kl + ((size_t)bh * MM + kvrow) * DHD;
    const bf16* gVh = Vh + ((size_t)bh * MM + kvrow) * DHD;
    const bf16* gVl = Vl + ((size_t)bh * MM + kvrow) * DHD;

    // prefetch KV chunk 0 into stage 0
    {
        #pragma unroll
        for (int si = 0; si < 2; si++) {
            const int seg = kvs0 + si;
            const uint32_t off = (uint32_t)(kvrow * 128 + ((seg ^ (kvrow & 7)) << 4));
            cp16(smem_base + off,            gKh + seg * 8);
            cp16(smem_base + FT_B + off,     gKl + seg * 8);
            cp16(smem_base + 2*FT_B + off,   gVh + seg * 8);
            cp16(smem_base + 3*FT_B + off,   gVl + seg * 8);
        }
        cp_commit();
        if (t < 64) sMk[0][t] = mask[(size_t)b * MM + t];
    }

    const int nIter = MM / 64;
    for (int nb = 0; nb < nIter; nb++) {
        const int cur = nb & 1;
        if (nb + 1 < nIter) {
            const size_t koff = (size_t)(nb + 1) * 64 * DHD;
            const uint32_t sb = smem_base + (cur ^ 1) * FSTAGE_B;
            #pragma unroll
            for (int si = 0; si < 2; si++) {
                const int seg = kvs0 + si;
                const uint32_t off = (uint32_t)(kvrow * 128 + ((seg ^ (kvrow & 7)) << 4));
                cp16(sb + off,            gKh + koff + seg * 8);
                cp16(sb + FT_B + off,     gKl + koff + seg * 8);
                cp16(sb + 2*FT_B + off,   gVh + koff + seg * 8);
                cp16(sb + 3*FT_B + off,   gVl + koff + seg * 8);
            }
            cp_commit();
            if (t < 64) sMk[cur ^ 1][t] = mask[(size_t)b * MM + (nb + 1) * 64 + t];
            cp_wait<1>();
        } else {
            cp_wait<0>();
        }
        __syncthreads();

        const uint32_t uK  = smem_base + cur * FSTAGE_B;
        const uint32_t uKl = uK + FT_B;
        const uint32_t uV  = uK + 2 * FT_B;
        const uint32_t uVl = uK + 3 * FT_B;

        // ---- S = Q @ K^T (3-pass split) ----
        float s[8][4];
        #pragma unroll
        for (int j = 0; j < 8; j++)
            #pragma unroll
            for (int e = 0; e < 4; e++) s[j][e] = 0.0f;

        #pragma unroll
        for (int kk = 0; kk < 4; kk++) {
            uint32_t kb[16], kbl[16];
            #pragma unroll
            for (int g = 0; g < 4; g++) {
                const int br = brow0 + g * 16;
                const int cc = kk * 2 + bcsel;
                const uint32_t off = (uint32_t)(br * 128 + ((cc ^ (br & 7)) << 4));
                ldsm4(&kb[g * 4],  uK + off);
                ldsm4(&kbl[g * 4], uKl + off);
            }
            #pragma unroll
            for (int j = 0; j < 8; j++) {
                mma16816(s[j], qfh[kk], &kb[j * 2]);
                mma16816(s[j], qfh[kk], &kbl[j * 2]);
                mma16816(s[j], qfl[kk], &kb[j * 2]);
            }
        }

        // ---- mask + online softmax ----
        const int c2 = (lane & 3) * 2;
        #pragma unroll
        for (int j = 0; j < 8; j++) {
            const float mka = sMk[cur][j * 8 + c2];
            const float mkb = sMk[cur][j * 8 + c2 + 1];
            s[j][0] += mka; s[j][1] += mkb; s[j][2] += mka; s[j][3] += mkb;
        }
        float mx0 = -1e30f, mx1 = -1e30f;
        #pragma unroll
        for (int j = 0; j < 8; j++) {
            mx0 = fmaxf(mx0, fmaxf(s[j][0], s[j][1]));
            mx1 = fmaxf(mx1, fmaxf(s[j][2], s[j][3]));
        }
        mx0 = fmaxf(mx0, __shfl_xor_sync(0xffffffffu, mx0, 1));
        mx0 = fmaxf(mx0, __shfl_xor_sync(0xffffffffu, mx0, 2));
        mx1 = fmaxf(mx1, __shfl_xor_sync(0xffffffffu, mx1, 1));
        mx1 = fmaxf(mx1, __shfl_xor_sync(0xffffffffu, mx1, 2));
        const float mn0 = fmaxf(m0, mx0);
        const float mn1 = fmaxf(m1, mx1);
        const float cr0 = __expf(m0 - mn0);
        const float cr1 = __expf(m1 - mn1);
        m0 = mn0; m1 = mn1;
        l0 *= cr0; l1 *= cr1;
        #pragma unroll
        for (int j = 0; j < 8; j++) {
            O[j][0] *= cr0; O[j][1] *= cr0;
            O[j][2] *= cr1; O[j][3] *= cr1;
        }

        // ---- P = exp(S - m), split+pack into A fragments ----
        uint32_t pahi[4][4], palo[4][4];
        #pragma unroll
        for (int j = 0; j < 8; j++) {
            const float p0 = __expf(s[j][0] - m0);
            const float p1 = __expf(s[j][1] - m0);
            const float p2 = __expf(s[j][2] - m1);
            const float p3 = __expf(s[j][3] - m1);
            l0 += p0 + p1;
            l1 += p2 + p3;
            const int kk = j >> 1, hf = (j & 1) * 2;
            split_pack(p0, p1, pahi[kk][hf],     palo[kk][hf]);
            split_pack(p2, p3, pahi[kk][hf + 1], palo[kk][hf + 1]);
        }

        // ---- O += P @ V (3-pass split) ----
        #pragma unroll
        for (int kk = 0; kk < 4; kk++) {
            uint32_t vh4[4][4], vl4[4][4];
            const int krow = kk * 16 + ((lane >> 3) & 1) * 8 + (lane & 7);
            #pragma unroll
            for (int g = 0; g < 4; g++) {
                const int cc = g * 2 + (lane >> 4);
                const uint32_t off = (uint32_t)(krow * 128 + ((cc ^ (krow & 7)) << 4));
                ldsm4t(vh4[g], uV + off);
                ldsm4t(vl4[g], uVl + off);
            }
            #pragma unroll
            for (int jn = 0; jn < 8; jn++) {
                const int g = jn >> 1, sub = (jn & 1) * 2;
                mma16816(O[jn], pahi[kk], &vh4[g][sub]);
                mma16816(O[jn], palo[kk], &vh4[g][sub]);
                mma16816(O[jn], pahi[kk], &vl4[g][sub]);
            }
        }
        __syncthreads();
    }

    // ---- epilogue ----
    l0 += __shfl_xor_sync(0xffffffffu, l0, 1);
    l0 += __shfl_xor_sync(0xffffffffu, l0, 2);
    l1 += __shfl_xor_sync(0xffffffffu, l1, 1);
    l1 += __shfl_xor_sync(0xffffffffu, l1, 2);
    const float inv0 = 1.0f / l0;
    const float inv1 = 1.0f / l1;

    const int mrow0 = qBase + wid * 16 + (lane >> 2);
    const int mrow1 = mrow0 + 8;
    #pragma unroll
    for (int jn = 0; jn < 8; jn++) {
        const int col = h * DHD + jn * 8 + (lane & 3) * 2;
        uint32_t h01, l01, h23, l23;
        split_pack(O[jn][0] * inv0, O[jn][1] * inv0, h01, l01);
        split_pack(O[jn][2] * inv1, O[jn][3] * inv1, h23, l23);
        const size_t i0 = ((size_t)b * MM + mrow0) * DM + col;
        const size_t i1 = ((size_t)b * MM + mrow1) * DM + col;
        *(uint32_t*)(out_hi + i0) = h01;
        *(uint32_t*)(out_lo + i0) = l01;
        *(uint32_t*)(out_hi + i1) = h23;
        *(uint32_t*)(out_lo + i1) = l23;
    }
}

// ---------------- LayerNorm(xa + xb) * g + b, over 768; optional split output ----------------
__global__ __launch_bounds__(256)
void ln_kernel(const float* __restrict__ xa, const float* __restrict__ xb,
               const float* __restrict__ gw, const float* __restrict__ bw,
               float* __restrict__ out, bf16* __restrict__ ohi, bf16* __restrict__ olo) {
    const int row = blockIdx.x;
    const int t = threadIdx.x;
    const float* pa = xa + (size_t)row * DM;
    const float* pb = xb + (size_t)row * DM;

    float v0 = pa[t]       + pb[t];
    float v1 = pa[t + 256] + pb[t + 256];
    float v2 = pa[t + 512] + pb[t + 512];

    float s  = v0 + v1 + v2;
    float ss = v0 * v0 + v1 * v1 + v2 * v2;
    #pragma unroll
    for (int off = 16; off > 0; off >>= 1) {
        s  += __shfl_xor_sync(0xffffffffu, s,  off);
        ss += __shfl_xor_sync(0xffffffffu, ss, off);
    }
    __shared__ float wsum[8], wsq[8], stats[2];
    int warp = t >> 5;
    if ((t & 31) == 0) { wsum[warp] = s; wsq[warp] = ss; }
    __syncthreads();
    if (t == 0) {
        float S = 0.f, SS = 0.f;
        #pragma unroll
        for (int w = 0; w < 8; w++) { S += wsum[w]; SS += wsq[w]; }
        float mu = S * (1.0f / DM);
        float var = SS * (1.0f / DM) - mu * mu;
        stats[0] = mu;
        stats[1] = rsqrtf(var + 1e-12f);
    }
    __syncthreads();
    float mu = stats[0], rstd = stats[1];
    float* po = out + (size_t)row * DM;
    float r0 = (v0 - mu) * rstd * gw[t]       + bw[t];
    float r1 = (v1 - mu) * rstd * gw[t + 256] + bw[t + 256];
    float r2 = (v2 - mu) * rstd * gw[t + 512] + bw[t + 512];
    po[t] = r0; po[t + 256] = r1; po[t + 512] = r2;
    if (ohi) {
        bf16 hh, ll;
        split2(r0, hh, ll); ohi[(size_t)row*DM + t]       = hh; olo[(size_t)row*DM + t]       = ll;
        split2(r1, hh, ll); ohi[(size_t)row*DM + t + 256] = hh; olo[(size_t)row*DM + t + 256] = ll;
        split2(r2, hh, ll); ohi[(size_t)row*DM + t + 512] = hh; olo[(size_t)row*DM + t + 512] = ll;
    }
}

// ---------------- launch ----------------
static inline void launch_mma(const bf16* Ahi, const bf16* Alo, const bf16* Bhi, const bf16* Blo,
                              const float* bias, float* Cf, bf16* Chi, bf16* Clo,
                              int Md, int Nd, int Kd, int doGelu) {
    dim3 grid(Nd / 128, Md / 128);
    mma_gemm_kernel<<<grid, 256, SMEM_GEMM>>>(Ahi, Alo, Bhi, Blo, bias, Cf, Chi, Clo,
                                              Md, Nd, Kd, doGelu);
}

extern "C" void kernel_launch(void* const* d_in, const int* in_sizes, int n_in,
                              void* d_out, int out_size) {
    const float* x    = (const float*)d_in[0];
    const float* mask = (const float*)d_in[1];
    const float* Pq   = (const float*)d_in[2];
    const float* Vq   = (const float*)d_in[3];
    const float* bq   = (const float*)d_in[4];
    const float* Pk   = (const float*)d_in[5];
    const float* Vk   = (const float*)d_in[6];
    const float* bk   = (const float*)d_in[7];
    const float* Pv   = (const float*)d_in[8];
    const float* Vv   = (const float*)d_in[9];
    const float* bv   = (const float*)d_in[10];
    const float* Uo   = (const float*)d_in[11];
    const float* Vo   = (const float*)d_in[12];
    const float* bo   = (const float*)d_in[13];
    const float* U1   = (const float*)d_in[14];
    const float* V1   = (const float*)d_in[15];
    const float* b1   = (const float*)d_in[16];
    const float* U2   = (const float*)d_in[17];
    const float* V2   = (const float*)d_in[18];
    const float* b2   = (const float*)d_in[19];
    const float* ln1g = (const float*)d_in[20];
    const float* ln1b = (const float*)d_in[21];
    const float* ln2g = (const float*)d_in[22];
    const float* ln2b = (const float*)d_in[23];

    static bool attrSet = false;
    if (!attrSet) {
        cudaFuncSetAttribute(mma_gemm_kernel, cudaFuncAttributeMaxDynamicSharedMemorySize, SMEM_GEMM);
        cudaFuncSetAttribute(flash_mma_kernel, cudaFuncAttributeMaxDynamicSharedMemorySize, SMEM_FLASH);
        attrSet = true;
    }

    float *pT, *pQ, *pK, *pV, *pTmp, *pX1;
    cudaGetSymbolAddress((void**)&pT,   g_T);
    cudaGetSymbolAddress((void**)&pQ,   g_Q);
    cudaGetSymbolAddress((void**)&pK,   g_K);
    cudaGetSymbolAddress((void**)&pV,   g_V);
    cudaGetSymbolAddress((void**)&pTmp, g_tmp);
    cudaGetSymbolAddress((void**)&pX1,  g_x1);

    bf16* qh = (bf16*)pQ;  bf16* ql = qh + (size_t)BMTOT * DM;
    bf16* kh = (bf16*)pK;  bf16* kl = kh + (size_t)BMTOT * DM;
    bf16* vh = (bf16*)pV;  bf16* vl = vh + (size_t)BMTOT * DM;

    bf16 *xsH,*xsL,*asH,*asL,*msH,*msL,*x1H,*x1L,*hsH,*hsL;
    bf16 *ptH,*ptL,*uoH,*uoL,*voH,*voL,*u1H,*u1L,*v1H,*v1L,*u2H,*u2L,*v2H,*v2L;
    cudaGetSymbolAddress((void**)&xsH, g_xs_hi);  cudaGetSymbolAddress((void**)&xsL, g_xs_lo);
    cudaGetSymbolAddress((void**)&asH, g_as_hi);  cudaGetSymbolAddress((void**)&asL, g_as_lo);
    cudaGetSymbolAddress((void**)&msH, g_ms_hi);  cudaGetSymbolAddress((void**)&msL, g_ms_lo);
    cudaGetSymbolAddress((void**)&x1H, g_x1s_hi); cudaGetSymbolAddress((void**)&x1L, g_x1s_lo);
    cudaGetSymbolAddress((void**)&hsH, g_hs_hi);  cudaGetSymbolAddress((void**)&hsL, g_hs_lo);
    cudaGetSymbolAddress((void**)&ptH, g_ptT_hi); cudaGetSymbolAddress((void**)&ptL, g_ptT_lo);
    cudaGetSymbolAddress((void**)&uoH, g_uoT_hi); cudaGetSymbolAddress((void**)&uoL, g_uoT_lo);
    cudaGetSymbolAddress((void**)&voH, g_voT_hi); cudaGetSymbolAddress((void**)&voL, g_voT_lo);
    cudaGetSymbolAddress((void**)&u1H, g_u1T_hi); cudaGetSymbolAddress((void**)&u1L, g_u1T_lo);
    cudaGetSymbolAddress((void**)&v1H, g_v1T_hi); cudaGetSymbolAddress((void**)&v1L, g_v1T_lo);
    cudaGetSymbolAddress((void**)&u2H, g_u2T_hi); cudaGetSymbolAddress((void**)&u2L, g_u2T_lo);
    cudaGetSymbolAddress((void**)&v2H, g_v2T_hi); cudaGetSymbolAddress((void**)&v2L, g_v2T_lo);

    // ---- weight conversions ----
    permutePtT_kernel<<<(NCAT * DM + 255) / 256, 256>>>(Pq, Pk, Pv, ptH, ptL);
    splitWT_kernel<<<(DM * RFF + 255) / 256, 256>>>(Uo, uoH, uoL, DM, RFF);
    splitWT_kernel<<<(RFF * DM + 255) / 256, 256>>>(Vo, voH, voL, RFF, DM);
    splitWT_kernel<<<(DM * RFF + 255) / 256, 256>>>(U1, u1H, u1L, DM, RFF);
    splitWT_kernel<<<(RFF * DFF + 255) / 256, 256>>>(V1, v1H, v1L, RFF, DFF);
    splitWT_kernel<<<(DFF * RFF + 255) / 256, 256>>>(U2, u2H, u2L, DFF, RFF);
    splitWT_kernel<<<(RFF * DM + 255) / 256, 256>>>(V2, v2H, v2L, RFF, DM);

    // ---- 1) split x; T = x @ Pt ----
    split_act_kernel<<<(BMTOT * DM / 4 + 255) / 256, 256>>>(x, xsH, xsL, BMTOT * DM / 4);
    launch_mma(xsH, xsL, ptH, ptL, nullptr, pT, nullptr, nullptr, BMTOT, NCAT, DM, 0);

    // ---- 2) QKV stage 2 (split bf16 out, Q pre-scaled) ----
    qkv2_kernel<<<dim3(BMTOT, 3), 256>>>(pT, Vq, Vk, Vv, bq, bk, bv, qh, ql, kh, kl, vh, vl);

    // ---- 3) tensor-core flash attention -> attn split ----
    flash_mma_kernel<<<dim3(MM / 128, BB * HH), 256, SMEM_FLASH>>>(qh, ql, kh, kl, vh, vl, mask, asH, asL);

    // ---- 4) Wo low-rank + LN1 ----
    launch_mma(asH, asL, uoH, uoL, nullptr, nullptr, msH, msL, BMTOT, RFF, DM, 0);
    launch_mma(msH, msL, voH, voL, bo, pTmp, nullptr, nullptr, BMTOT, DM, RFF, 0);
    ln_kernel<<<BMTOT, 256>>>(x, pTmp, ln1g, ln1b, pX1, x1H, x1L);

    // ---- 5) FFN ----
    launch_mma(x1H, x1L, u1H, u1L, nullptr, nullptr, msH, msL, BMTOT, RFF, DM, 0);
    launch_mma(msH, msL, v1H, v1L, b1, nullptr, hsH, hsL, BMTOT, DFF, RFF, 1);
    launch_mma(hsH, hsL, u2H, u2L, nullptr, nullptr, msH, msL, BMTOT, RFF, DFF, 0);
    launch_mma(msH, msL, v2H, v2L, b2, pTmp, nullptr, nullptr, BMTOT, DM, RFF, 0);
    ln_kernel<<<BMTOT, 256>>>(pX1, pTmp, ln2g, ln2b, (float*)d_out, nullptr, nullptr);
}